// round 1
// baseline (speedup 1.0000x reference)
#include <cuda_runtime.h>
#include <cstdint>
#include <math.h>

#define B_   2
#define T_   2048
#define C_   2048
#define H_   16
#define D_   128
#define HALF_ 64
#define M_   (B_*T_)       // 4096 rows
#define N1_  (3*C_)        // 6144
#define RS_  (3*C_)        // qkv row stride

// ---------------- scratch (device globals; no cudaMalloc allowed) ----------------
__device__ float g_qkv[(size_t)M_ * N1_];    // [B*T, 3*C]  ~100.7 MB
__device__ float g_attn[(size_t)M_ * C_];    // flat (B,H,T,D) order  ~33.5 MB
__device__ float g_sin[T_ * HALF_];
__device__ float g_cos[T_ * HALF_];

// ---------------- fast exp (FFMA-pipe, avoids MUFU throughput wall) --------------
__device__ __forceinline__ float fast_exp(float x) {
    x = fmaxf(x, -87.0f);                       // also neutralizes -inf / -3.4e38 masks
    float t = x * 1.4426950408889634f;          // x * log2(e)
    int   i = __float2int_rn(t);
    float f = t - (float)i;                     // |f| <= 0.5
    float p =          1.3333558146428443e-3f;  // Taylor of 2^f, rel err ~2.4e-6
    p = fmaf(p, f, 9.6181291780723730e-3f);
    p = fmaf(p, f, 5.5504108664821580e-2f);
    p = fmaf(p, f, 2.4022650695910072e-1f);
    p = fmaf(p, f, 6.9314718055994531e-1f);
    p = fmaf(p, f, 1.0f);
    return __int_as_float((i + 127) << 23) * p;
}

// ---------------- SGEMM 128x128x8, double-buffered smem, 8x8 per thread ----------
__global__ void __launch_bounds__(256) sgemm128(const float* __restrict__ A,
                                                const float* __restrict__ B,
                                                float* __restrict__ C,
                                                int M, int N, int K)
{
    __shared__ float As[2][8][132];   // transposed A tile, padded (conflict-free)
    __shared__ float Bs[2][8][128];

    const int tid = threadIdx.x;
    const int bx = blockIdx.x, by = blockIdx.y;

    const int trow = (tid >> 4) << 3;     // 0..120
    const int tcol = (tid & 15) << 3;

    const int arow = tid >> 1;            // 0..127
    const int ak   = (tid & 1) << 2;      // 0 or 4
    const int brow = tid >> 5;            // 0..7
    const int bcol = (tid & 31) << 2;     // 0..124

    const float* Ag = A + (size_t)(by * 128 + arow) * K + ak;
    const float* Bg = B + (size_t)brow * N + bx * 128 + bcol;

    float acc[8][8];
#pragma unroll
    for (int i = 0; i < 8; i++)
#pragma unroll
        for (int j = 0; j < 8; j++) acc[i][j] = 0.f;

    float4 av = *(const float4*)Ag;
    float4 bv = *(const float4*)Bg;
    int buf = 0;
    As[buf][ak + 0][arow] = av.x;
    As[buf][ak + 1][arow] = av.y;
    As[buf][ak + 2][arow] = av.z;
    As[buf][ak + 3][arow] = av.w;
    *(float4*)&Bs[buf][brow][bcol] = bv;
    __syncthreads();

    const int KT = K >> 3;
    for (int kt = 0; kt < KT; kt++) {
        float4 av2, bv2;
        const bool more = (kt + 1 < KT);
        if (more) {
            av2 = *(const float4*)(Ag + ((kt + 1) << 3));
            bv2 = *(const float4*)(Bg + (size_t)((kt + 1) << 3) * N);
        }
#pragma unroll
        for (int k = 0; k < 8; k++) {
            float4 a0 = *(const float4*)&As[buf][k][trow];
            float4 a1 = *(const float4*)&As[buf][k][trow + 4];
            float4 b0 = *(const float4*)&Bs[buf][k][tcol];
            float4 b1 = *(const float4*)&Bs[buf][k][tcol + 4];
            float ar[8] = {a0.x, a0.y, a0.z, a0.w, a1.x, a1.y, a1.z, a1.w};
            float br[8] = {b0.x, b0.y, b0.z, b0.w, b1.x, b1.y, b1.z, b1.w};
#pragma unroll
            for (int i = 0; i < 8; i++)
#pragma unroll
                for (int j = 0; j < 8; j++)
                    acc[i][j] = fmaf(ar[i], br[j], acc[i][j]);
        }
        buf ^= 1;
        if (more) {
            As[buf][ak + 0][arow] = av2.x;
            As[buf][ak + 1][arow] = av2.y;
            As[buf][ak + 2][arow] = av2.z;
            As[buf][ak + 3][arow] = av2.w;
            *(float4*)&Bs[buf][brow][bcol] = bv2;
        }
        __syncthreads();
    }

    float* Cg = C + (size_t)(by * 128 + trow) * N + bx * 128 + tcol;
#pragma unroll
    for (int i = 0; i < 8; i++) {
        float4 c0 = {acc[i][0], acc[i][1], acc[i][2], acc[i][3]};
        float4 c1 = {acc[i][4], acc[i][5], acc[i][6], acc[i][7]};
        *(float4*)(Cg + (size_t)i * N)     = c0;
        *(float4*)(Cg + (size_t)i * N + 4) = c1;
    }
}

// ---------------- RoPE tables (fp64 angles to match fp32 ref within ~1 ulp) ------
__global__ void rope_table_kernel()
{
    int idx = blockIdx.x * blockDim.x + threadIdx.x;
    if (idx >= T_ * HALF_) return;
    int t = idx / HALF_, j = idx % HALF_;
    double div  = exp(-(double)(2 * j) * 9.210340371976184 / 128.0); // ln(10000)
    float  divf = (float)div;
    float  angf = (float)t * divf;        // emulate jax fp32 pos*div
    g_sin[idx] = (float)sin((double)angf);
    g_cos[idx] = (float)cos((double)angf);
}

__global__ void rope_apply_kernel()
{
    int idx = blockIdx.x * blockDim.x + threadIdx.x;   // ((b*T+t)*H + h)*HALF + j
    int j  = idx & (HALF_ - 1);
    int h  = (idx >> 6) & (H_ - 1);
    int bt = idx >> 10;                    // b*T + t
    int t  = bt & (T_ - 1);
    float sn = g_sin[t * HALF_ + j];
    float cs = g_cos[t * HALF_ + j];
    size_t base = (size_t)bt * RS_ + h * D_;
    float* q = g_qkv + base;
    float q1 = q[j], q2 = q[j + HALF_];
    q[j]         = q1 * cs - q2 * sn;
    q[j + HALF_] = q2 * cs + q1 * sn;
    float* k = g_qkv + base + C_;
    float k1 = k[j], k2 = k[j + HALF_];
    k[j]         = k1 * cs - k2 * sn;
    k[j + HALF_] = k2 * cs + k1 * sn;
}

// ---------------- causal flash attention, 64x64 tiles, 256 threads ---------------
__global__ void __launch_bounds__(256) flash_kernel()
{
    __shared__ float sm[8704];            // 34816 B, phase-union
    float* QcT = sm;                      // [32][68]  (phase A)
    float* KcT = sm + 32 * 68;            // [32][68]
    float* Ps  = sm;                      // [64][68]  (phase B, aliases QcT/KcT)
    float* Vh  = sm + 64 * 68;            // [64][68]

    const int i0 = blockIdx.x;            // query tile
    const int bh = blockIdx.y;
    const int b = bh >> 4, h = bh & 15;
    const int tid = threadIdx.x;
    const int tx = tid & 15, ty = tid >> 4;

    const float scale = 0.088388347648318447f;   // 1/sqrt(128)
    const size_t qbase  = ((size_t)(b * T_) + (size_t)i0 * 64) * RS_ + h * D_;
    const size_t kbase0 = (size_t)(b * T_) * RS_ + C_ + h * D_;
    const size_t vbase0 = (size_t)(b * T_) * RS_ + 2 * C_ + h * D_;

    float o[4][8];
    float m[4], l[4];
#pragma unroll
    for (int i = 0; i < 4; i++) {
        m[i] = -3.4e38f; l[i] = 0.f;
#pragma unroll
        for (int c = 0; c < 8; c++) o[i][c] = 0.f;
    }

    const int ldr  = tid >> 2;            // 0..63
    const int lddg = (tid & 3) * 8;       // d-group for QK chunk loads
    const int ldcg = (tid & 3) * 16;      // col-group for V loads

    for (int j0 = 0; j0 <= i0; j0++) {
        float s[4][4];
#pragma unroll
        for (int i = 0; i < 4; i++)
#pragma unroll
            for (int j = 0; j < 4; j++) s[i][j] = 0.f;

        const size_t kbase = kbase0 + (size_t)(j0 * 64) * RS_;

        // ---- phase A: S = Q K^T (d chunks of 32, transposed smem tiles) ----
        for (int d0 = 0; d0 < D_; d0 += 32) {
            __syncthreads();
            {
                const float* gq = g_qkv + qbase + (size_t)ldr * RS_ + d0 + lddg;
                const float* gk = g_qkv + kbase + (size_t)ldr * RS_ + d0 + lddg;
                float4 q0 = *(const float4*)gq;
                float4 q1 = *(const float4*)(gq + 4);
                float4 k0 = *(const float4*)gk;
                float4 k1 = *(const float4*)(gk + 4);
                QcT[(lddg + 0) * 68 + ldr] = q0.x;
                QcT[(lddg + 1) * 68 + ldr] = q0.y;
                QcT[(lddg + 2) * 68 + ldr] = q0.z;
                QcT[(lddg + 3) * 68 + ldr] = q0.w;
                QcT[(lddg + 4) * 68 + ldr] = q1.x;
                QcT[(lddg + 5) * 68 + ldr] = q1.y;
                QcT[(lddg + 6) * 68 + ldr] = q1.z;
                QcT[(lddg + 7) * 68 + ldr] = q1.w;
                KcT[(lddg + 0) * 68 + ldr] = k0.x;
                KcT[(lddg + 1) * 68 + ldr] = k0.y;
                KcT[(lddg + 2) * 68 + ldr] = k0.z;
                KcT[(lddg + 3) * 68 + ldr] = k0.w;
                KcT[(lddg + 4) * 68 + ldr] = k1.x;
                KcT[(lddg + 5) * 68 + ldr] = k1.y;
                KcT[(lddg + 6) * 68 + ldr] = k1.z;
                KcT[(lddg + 7) * 68 + ldr] = k1.w;
            }
            __syncthreads();
#pragma unroll
            for (int d = 0; d < 32; d++) {
                float4 qv = *(const float4*)&QcT[d * 68 + ty * 4];
                float4 kv = *(const float4*)&KcT[d * 68 + tx * 4];
                float qa[4] = {qv.x, qv.y, qv.z, qv.w};
                float ka[4] = {kv.x, kv.y, kv.z, kv.w};
#pragma unroll
                for (int i = 0; i < 4; i++)
#pragma unroll
                    for (int j = 0; j < 4; j++)
                        s[i][j] = fmaf(qa[i], ka[j], s[i][j]);
            }
        }

        // ---- online softmax (row stats across the 16-lane tx groups) ----
        const bool diag = (j0 == i0);
#pragma unroll
        for (int i = 0; i < 4; i++) {
            float mloc = -3.4e38f;
#pragma unroll
            for (int j = 0; j < 4; j++) {
                float v = s[i][j] * scale;
                if (diag && (tx * 4 + j > ty * 4 + i)) v = -3.4e38f;
                s[i][j] = v;
                mloc = fmaxf(mloc, v);
            }
#pragma unroll
            for (int off = 8; off > 0; off >>= 1)
                mloc = fmaxf(mloc, __shfl_xor_sync(0xffffffffu, mloc, off, 16));
            float mnew  = fmaxf(m[i], mloc);
            float alpha = fast_exp(m[i] - mnew);
            float lsum  = 0.f;
#pragma unroll
            for (int j = 0; j < 4; j++) {
                float p = fast_exp(s[i][j] - mnew);
                s[i][j] = p;
                lsum += p;
            }
#pragma unroll
            for (int off = 8; off > 0; off >>= 1)
                lsum += __shfl_xor_sync(0xffffffffu, lsum, off, 16);
            l[i] = l[i] * alpha + lsum;
            m[i] = mnew;
#pragma unroll
            for (int c = 0; c < 8; c++) o[i][c] *= alpha;
        }

        __syncthreads();  // phase A smem reads done -> safe to alias as Ps
#pragma unroll
        for (int i = 0; i < 4; i++)
#pragma unroll
            for (int j = 0; j < 4; j++)
                Ps[(ty * 4 + i) * 68 + tx * 4 + j] = s[i][j];

        // ---- phase B: O += P V, V in two 64-col halves ----
        const size_t vbase = vbase0 + (size_t)(j0 * 64) * RS_;
#pragma unroll
        for (int hf = 0; hf < 2; hf++) {
            {
                const float* gv = g_qkv + vbase + (size_t)ldr * RS_ + hf * 64 + ldcg;
                float4 v0 = *(const float4*)gv;
                float4 v1 = *(const float4*)(gv + 4);
                float4 v2 = *(const float4*)(gv + 8);
                float4 v3 = *(const float4*)(gv + 12);
                float* dst = &Vh[ldr * 68 + ldcg];
                *(float4*)(dst)      = v0;
                *(float4*)(dst + 4)  = v1;
                *(float4*)(dst + 8)  = v2;
                *(float4*)(dst + 12) = v3;
            }
            __syncthreads();
            for (int k = 0; k < 64; k++) {
                float4 v = *(const float4*)&Vh[k * 68 + tx * 4];
#pragma unroll
                for (int i = 0; i < 4; i++) {
                    float p = Ps[(ty * 4 + i) * 68 + k];
                    o[i][hf * 4 + 0] = fmaf(p, v.x, o[i][hf * 4 + 0]);
                    o[i][hf * 4 + 1] = fmaf(p, v.y, o[i][hf * 4 + 1]);
                    o[i][hf * 4 + 2] = fmaf(p, v.z, o[i][hf * 4 + 2]);
                    o[i][hf * 4 + 3] = fmaf(p, v.w, o[i][hf * 4 + 3]);
                }
            }
            __syncthreads();
        }
    }

    // ---- epilogue: write attention output in flat (B,H,T,D) order (matches ref reshape) ----
#pragma unroll
    for (int i = 0; i < 4; i++) {
        float inv = 1.f / l[i];
        int gr = i0 * 64 + ty * 4 + i;
        float* dst = g_attn + (((size_t)(b * H_ + h) * T_ + gr) * D_);
        float4 o0 = {o[i][0] * inv, o[i][1] * inv, o[i][2] * inv, o[i][3] * inv};
        float4 o1 = {o[i][4] * inv, o[i][5] * inv, o[i][6] * inv, o[i][7] * inv};
        *(float4*)(dst + tx * 4)      = o0;
        *(float4*)(dst + 64 + tx * 4) = o1;
    }
}

// ---------------- launch ----------------
extern "C" void kernel_launch(void* const* d_in, const int* in_sizes, int n_in,
                              void* d_out, int out_size)
{
    const float* x    = (const float*)d_in[0];
    const float* Wqkv = (const float*)d_in[1];
    const float* Wout = (const float*)d_in[2];
    float* out = (float*)d_out;

    float *qkv = nullptr, *attn = nullptr;
    cudaGetSymbolAddress((void**)&qkv,  g_qkv);
    cudaGetSymbolAddress((void**)&attn, g_attn);

    // 1) QKV projection: [4096,2048] @ [2048,6144]
    sgemm128<<<dim3(N1_ / 128, M_ / 128), 256>>>(x, Wqkv, qkv, M_, N1_, C_);
    // 2) RoPE tables + apply
    rope_table_kernel<<<(T_ * HALF_ + 255) / 256, 256>>>();
    rope_apply_kernel<<<(B_ * T_ * H_ * HALF_) / 256, 256>>>();
    // 3) causal flash attention
    flash_kernel<<<dim3(T_ / 64, B_ * H_), 256>>>();
    // 4) output projection: [4096,2048] @ [2048,2048]
    sgemm128<<<dim3(C_ / 128, M_ / 128), 256>>>(attn, Wout, out, M_, C_, C_);
}

// round 2
// speedup vs baseline: 1.7527x; 1.7527x over previous
#include <cuda_runtime.h>
#include <cuda_bf16.h>
#include <cstdint>
#include <math.h>

#define B_   2
#define T_   2048
#define C_   2048
#define H_   16
#define D_   128
#define HALF_ 64
#define M_   (B_*T_)       // 4096 rows
#define N1_  (3*C_)        // 6144
#define RS_  (3*C_)        // qkv row stride

// ---------------- scratch (device globals; no cudaMalloc allowed) ----------------
__device__ float g_qkv[(size_t)M_ * N1_];    // [B*T, 3*C]
__device__ float g_attn[(size_t)M_ * C_];    // flat (B,H,T,D) order
__device__ float g_sin[T_ * HALF_];
__device__ float g_cos[T_ * HALF_];

// ---------------- fast exp (FFMA-pipe, avoids MUFU throughput wall) --------------
__device__ __forceinline__ float fast_exp(float x) {
    x = fmaxf(x, -87.0f);
    float t = x * 1.4426950408889634f;
    int   i = __float2int_rn(t);
    float f = t - (float)i;
    float p =          1.3333558146428443e-3f;
    p = fmaf(p, f, 9.6181291780723730e-3f);
    p = fmaf(p, f, 5.5504108664821580e-2f);
    p = fmaf(p, f, 2.4022650695910072e-1f);
    p = fmaf(p, f, 6.9314718055994531e-1f);
    p = fmaf(p, f, 1.0f);
    return __int_as_float((i + 127) << 23) * p;
}

// =================================================================================
//  bf16x3 split-precision tensor-core GEMM:  C = A @ B  (fp32 in/out, ~1e-5 accurate)
//  BM=128 BN=128 BK=64, 256 threads (8 warps, 64x32 warp tiles), mma.m16n8k16
// =================================================================================

#define LDSM_X4(R0,R1,R2,R3,ADDR) \
    asm volatile("ldmatrix.sync.aligned.m8n8.x4.shared.b16 {%0,%1,%2,%3}, [%4];" \
                 : "=r"(R0), "=r"(R1), "=r"(R2), "=r"(R3) : "r"(ADDR))
#define LDSM_X4_T(R0,R1,R2,R3,ADDR) \
    asm volatile("ldmatrix.sync.aligned.m8n8.x4.trans.shared.b16 {%0,%1,%2,%3}, [%4];" \
                 : "=r"(R0), "=r"(R1), "=r"(R2), "=r"(R3) : "r"(ADDR))

__device__ __forceinline__ void mma16816(float* d, const unsigned* a, const unsigned* b) {
    asm volatile(
        "mma.sync.aligned.m16n8k16.row.col.f32.bf16.bf16.f32 "
        "{%0,%1,%2,%3}, {%4,%5,%6,%7}, {%8,%9}, {%0,%1,%2,%3};"
        : "+f"(d[0]), "+f"(d[1]), "+f"(d[2]), "+f"(d[3])
        : "r"(a[0]), "r"(a[1]), "r"(a[2]), "r"(a[3]), "r"(b[0]), "r"(b[1]));
}

// split fp32 pair -> packed bf16x2 hi and lo
__device__ __forceinline__ void split2(float x, float y, unsigned& hi, unsigned& lo) {
    __nv_bfloat162 h2 = __floats2bfloat162_rn(x, y);
    float hx = __bfloat162float(h2.x);
    float hy = __bfloat162float(h2.y);
    __nv_bfloat162 l2 = __floats2bfloat162_rn(x - hx, y - hy);
    hi = *reinterpret_cast<unsigned*>(&h2);
    lo = *reinterpret_cast<unsigned*>(&l2);
}

// smem stage layout (bytes): [Ahi 16K][Alo 16K][Bhi 16K][Blo 16K] per buffer
#define S_ALO 16384
#define S_BHI 32768
#define S_BLO 49152
#define STAGE_ 65536

__device__ __forceinline__ void load_stage(const float* ap, const float* bp,
                                           int K, int N, uint4* sa, uint4* sb) {
#pragma unroll
    for (int i = 0; i < 4; i++) {
        const uint4* p = (const uint4*)(ap + (size_t)(32 * i) * K);
        sa[2 * i]     = p[0];
        sa[2 * i + 1] = p[1];
        const uint4* q = (const uint4*)(bp + (size_t)(16 * i) * N);
        sb[2 * i]     = q[0];
        sb[2 * i + 1] = q[1];
    }
}

__device__ __forceinline__ void store_stage(char* s, const uint4* sa, const uint4* sb,
                                            int aoff, int boff) {
#pragma unroll
    for (int i = 0; i < 4; i++) {
        const float* f = (const float*)&sa[2 * i];
        unsigned h[4], l[4];
#pragma unroll
        for (int j = 0; j < 4; j++) split2(f[2 * j], f[2 * j + 1], h[j], l[j]);
        *(uint4*)(s + aoff + i * 4096)          = make_uint4(h[0], h[1], h[2], h[3]);
        *(uint4*)(s + S_ALO + aoff + i * 4096)  = make_uint4(l[0], l[1], l[2], l[3]);
        const float* g = (const float*)&sb[2 * i];
#pragma unroll
        for (int j = 0; j < 4; j++) split2(g[2 * j], g[2 * j + 1], h[j], l[j]);
        *(uint4*)(s + S_BHI + boff + i * 4096)  = make_uint4(h[0], h[1], h[2], h[3]);
        *(uint4*)(s + S_BLO + boff + i * 4096)  = make_uint4(l[0], l[1], l[2], l[3]);
    }
}

__global__ void __launch_bounds__(256) mma_gemm(const float* __restrict__ A,
                                                const float* __restrict__ B,
                                                float* __restrict__ C,
                                                int M, int N, int K)
{
    extern __shared__ char smem[];
    const uint32_t smem_u32 = (uint32_t)__cvta_generic_to_shared(smem);

    const int tid  = threadIdx.x;
    const int lane = tid & 31;
    const int wid  = tid >> 5;
    const int warp_m = wid & 1;        // 0..1  (64 rows each)
    const int warp_n = wid >> 1;       // 0..3  (32 cols each)
    const int quad = lane >> 3;
    const int rq   = lane & 7;

    const int bm = blockIdx.y * 128;
    const int bn = blockIdx.x * 128;

    // ---- global staging coordinates ----
    const int rA  = tid >> 3;          // A row within tile (0..31, +32i)
    const int kbA = tid & 7;           // A k-chunk (8 floats)
    const int kB  = tid >> 4;          // B k row within tile (0..15, +16i)
    const int nbB = tid & 15;          // B n-chunk (8 floats)

    const float* Aq = A + (size_t)(bm + rA) * K + kbA * 8;
    const float* Bq = B + (size_t)kB * N + bn + nbB * 8;

    // ---- swizzled STS byte offsets (within region) ----
    const int aoff = rA * 128 + (kbA ^ (rA & 7)) * 16;
    const int boff = kB * 256 + (((nbB & 8) | ((nbB & 7) ^ (kB & 7)))) * 16;

    // ---- ldmatrix lane addressing ----
    const int aRowL = warp_m * 64 + (quad & 1) * 8 + rq;   // A row for this lane
    const int kHalf = quad >> 1;                            // 0/1: +8 in k
    const int arow7 = aRowL & 7;
    const int arowByte = aRowL * 128;

    const int kL = (quad & 1) * 8 + rq;                     // B k row for this lane
    int nbswp[2];
#pragma unroll
    for (int p = 0; p < 2; p++) {
        int nb = warp_n * 4 + (quad >> 1) + p * 2;          // (warp_n*32 + (quad>>1)*8 + p*16)>>3
        nbswp[p] = (nb & 8) | ((nb & 7) ^ (kL & 7));
    }
    const int bByteBase = kL * 256;

    float acc[4][4][4];
#pragma unroll
    for (int mt = 0; mt < 4; mt++)
#pragma unroll
        for (int nt = 0; nt < 4; nt++)
#pragma unroll
            for (int c = 0; c < 4; c++) acc[mt][nt][c] = 0.f;

    uint4 sa[8], sb[8];
    load_stage(Aq, Bq, K, N, sa, sb);
    store_stage(smem, sa, sb, aoff, boff);
    __syncthreads();

    const int KT = K >> 6;
    int buf = 0;
    for (int kt = 0; kt < KT; kt++) {
        const bool more = (kt + 1 < KT);
        if (more)
            load_stage(Aq + (kt + 1) * 64, Bq + (size_t)(kt + 1) * 64 * N, K, N, sa, sb);

        const uint32_t sbase = smem_u32 + buf * STAGE_;
#pragma unroll
        for (int kk = 0; kk < 4; kk++) {
            unsigned ah[4][4], al[4][4], bh[2][4], bl[2][4];
            const int asw = ((2 * kk + kHalf) ^ arow7) * 16;
#pragma unroll
            for (int mt = 0; mt < 4; mt++) {
                uint32_t ad = sbase + arowByte + mt * 2048 + asw;
                LDSM_X4(ah[mt][0], ah[mt][1], ah[mt][2], ah[mt][3], ad);
                LDSM_X4(al[mt][0], al[mt][1], al[mt][2], al[mt][3], ad + S_ALO);
            }
#pragma unroll
            for (int p = 0; p < 2; p++) {
                uint32_t bd = sbase + kk * 4096 + bByteBase + nbswp[p] * 16;
                LDSM_X4_T(bh[p][0], bh[p][1], bh[p][2], bh[p][3], bd + S_BHI);
                LDSM_X4_T(bl[p][0], bl[p][1], bl[p][2], bl[p][3], bd + S_BLO);
            }
#pragma unroll
            for (int mt = 0; mt < 4; mt++)
#pragma unroll
                for (int nt = 0; nt < 4; nt++) {
                    const unsigned* bph = &bh[nt >> 1][(nt & 1) * 2];
                    const unsigned* bpl = &bl[nt >> 1][(nt & 1) * 2];
                    mma16816(acc[mt][nt], ah[mt], bph);
                    mma16816(acc[mt][nt], al[mt], bph);
                    mma16816(acc[mt][nt], ah[mt], bpl);
                }
        }

        if (more) store_stage(smem + (buf ^ 1) * STAGE_, sa, sb, aoff, boff);
        __syncthreads();
        buf ^= 1;
    }

    // ---- epilogue ----
    const int r0 = bm + warp_m * 64 + (lane >> 2);
    const int c0 = bn + warp_n * 32 + (lane & 3) * 2;
#pragma unroll
    for (int mt = 0; mt < 4; mt++)
#pragma unroll
        for (int nt = 0; nt < 4; nt++) {
            float* p0 = C + (size_t)(r0 + mt * 16) * N + c0 + nt * 8;
            float* p1 = C + (size_t)(r0 + mt * 16 + 8) * N + c0 + nt * 8;
            *(float2*)p0 = make_float2(acc[mt][nt][0], acc[mt][nt][1]);
            *(float2*)p1 = make_float2(acc[mt][nt][2], acc[mt][nt][3]);
        }
}

// ---------------- RoPE tables (fp64 angles to match fp32 ref within ~1 ulp) ------
__global__ void rope_table_kernel()
{
    int idx = blockIdx.x * blockDim.x + threadIdx.x;
    if (idx >= T_ * HALF_) return;
    int t = idx / HALF_, j = idx % HALF_;
    double div  = exp(-(double)(2 * j) * 9.210340371976184 / 128.0);
    float  divf = (float)div;
    float  angf = (float)t * divf;
    g_sin[idx] = (float)sin((double)angf);
    g_cos[idx] = (float)cos((double)angf);
}

__global__ void rope_apply_kernel()
{
    int idx = blockIdx.x * blockDim.x + threadIdx.x;
    int j  = idx & (HALF_ - 1);
    int h  = (idx >> 6) & (H_ - 1);
    int bt = idx >> 10;
    int t  = bt & (T_ - 1);
    float sn = g_sin[t * HALF_ + j];
    float cs = g_cos[t * HALF_ + j];
    size_t base = (size_t)bt * RS_ + h * D_;
    float* q = g_qkv + base;
    float q1 = q[j], q2 = q[j + HALF_];
    q[j]         = q1 * cs - q2 * sn;
    q[j + HALF_] = q2 * cs + q1 * sn;
    float* k = g_qkv + base + C_;
    float k1 = k[j], k2 = k[j + HALF_];
    k[j]         = k1 * cs - k2 * sn;
    k[j + HALF_] = k2 * cs + k1 * sn;
}

// ---------------- causal flash attention, 64x64 tiles, 256 threads ---------------
__global__ void __launch_bounds__(256) flash_kernel()
{
    __shared__ float sm[8704];
    float* QcT = sm;
    float* KcT = sm + 32 * 68;
    float* Ps  = sm;
    float* Vh  = sm + 64 * 68;

    const int i0 = blockIdx.x;
    const int bh = blockIdx.y;
    const int b = bh >> 4, h = bh & 15;
    const int tid = threadIdx.x;
    const int tx = tid & 15, ty = tid >> 4;

    const float scale = 0.088388347648318447f;
    const size_t qbase  = ((size_t)(b * T_) + (size_t)i0 * 64) * RS_ + h * D_;
    const size_t kbase0 = (size_t)(b * T_) * RS_ + C_ + h * D_;
    const size_t vbase0 = (size_t)(b * T_) * RS_ + 2 * C_ + h * D_;

    float o[4][8];
    float m[4], l[4];
#pragma unroll
    for (int i = 0; i < 4; i++) {
        m[i] = -3.4e38f; l[i] = 0.f;
#pragma unroll
        for (int c = 0; c < 8; c++) o[i][c] = 0.f;
    }

    const int ldr  = tid >> 2;
    const int lddg = (tid & 3) * 8;
    const int ldcg = (tid & 3) * 16;

    for (int j0 = 0; j0 <= i0; j0++) {
        float s[4][4];
#pragma unroll
        for (int i = 0; i < 4; i++)
#pragma unroll
            for (int j = 0; j < 4; j++) s[i][j] = 0.f;

        const size_t kbase = kbase0 + (size_t)(j0 * 64) * RS_;

        for (int d0 = 0; d0 < D_; d0 += 32) {
            __syncthreads();
            {
                const float* gq = g_qkv + qbase + (size_t)ldr * RS_ + d0 + lddg;
                const float* gk = g_qkv + kbase + (size_t)ldr * RS_ + d0 + lddg;
                float4 q0 = *(const float4*)gq;
                float4 q1 = *(const float4*)(gq + 4);
                float4 k0 = *(const float4*)gk;
                float4 k1 = *(const float4*)(gk + 4);
                QcT[(lddg + 0) * 68 + ldr] = q0.x;
                QcT[(lddg + 1) * 68 + ldr] = q0.y;
                QcT[(lddg + 2) * 68 + ldr] = q0.z;
                QcT[(lddg + 3) * 68 + ldr] = q0.w;
                QcT[(lddg + 4) * 68 + ldr] = q1.x;
                QcT[(lddg + 5) * 68 + ldr] = q1.y;
                QcT[(lddg + 6) * 68 + ldr] = q1.z;
                QcT[(lddg + 7) * 68 + ldr] = q1.w;
                KcT[(lddg + 0) * 68 + ldr] = k0.x;
                KcT[(lddg + 1) * 68 + ldr] = k0.y;
                KcT[(lddg + 2) * 68 + ldr] = k0.z;
                KcT[(lddg + 3) * 68 + ldr] = k0.w;
                KcT[(lddg + 4) * 68 + ldr] = k1.x;
                KcT[(lddg + 5) * 68 + ldr] = k1.y;
                KcT[(lddg + 6) * 68 + ldr] = k1.z;
                KcT[(lddg + 7) * 68 + ldr] = k1.w;
            }
            __syncthreads();
#pragma unroll
            for (int d = 0; d < 32; d++) {
                float4 qv = *(const float4*)&QcT[d * 68 + ty * 4];
                float4 kv = *(const float4*)&KcT[d * 68 + tx * 4];
                float qa[4] = {qv.x, qv.y, qv.z, qv.w};
                float ka[4] = {kv.x, kv.y, kv.z, kv.w};
#pragma unroll
                for (int i = 0; i < 4; i++)
#pragma unroll
                    for (int j = 0; j < 4; j++)
                        s[i][j] = fmaf(qa[i], ka[j], s[i][j]);
            }
        }

        const bool diag = (j0 == i0);
#pragma unroll
        for (int i = 0; i < 4; i++) {
            float mloc = -3.4e38f;
#pragma unroll
            for (int j = 0; j < 4; j++) {
                float v = s[i][j] * scale;
                if (diag && (tx * 4 + j > ty * 4 + i)) v = -3.4e38f;
                s[i][j] = v;
                mloc = fmaxf(mloc, v);
            }
#pragma unroll
            for (int off = 8; off > 0; off >>= 1)
                mloc = fmaxf(mloc, __shfl_xor_sync(0xffffffffu, mloc, off, 16));
            float mnew  = fmaxf(m[i], mloc);
            float alpha = fast_exp(m[i] - mnew);
            float lsum  = 0.f;
#pragma unroll
            for (int j = 0; j < 4; j++) {
                float p = fast_exp(s[i][j] - mnew);
                s[i][j] = p;
                lsum += p;
            }
#pragma unroll
            for (int off = 8; off > 0; off >>= 1)
                lsum += __shfl_xor_sync(0xffffffffu, lsum, off, 16);
            l[i] = l[i] * alpha + lsum;
            m[i] = mnew;
#pragma unroll
            for (int c = 0; c < 8; c++) o[i][c] *= alpha;
        }

        __syncthreads();
#pragma unroll
        for (int i = 0; i < 4; i++)
#pragma unroll
            for (int j = 0; j < 4; j++)
                Ps[(ty * 4 + i) * 68 + tx * 4 + j] = s[i][j];

        const size_t vbase = vbase0 + (size_t)(j0 * 64) * RS_;
#pragma unroll
        for (int hf = 0; hf < 2; hf++) {
            {
                const float* gv = g_qkv + vbase + (size_t)ldr * RS_ + hf * 64 + ldcg;
                float4 v0 = *(const float4*)gv;
                float4 v1 = *(const float4*)(gv + 4);
                float4 v2 = *(const float4*)(gv + 8);
                float4 v3 = *(const float4*)(gv + 12);
                float* dst = &Vh[ldr * 68 + ldcg];
                *(float4*)(dst)      = v0;
                *(float4*)(dst + 4)  = v1;
                *(float4*)(dst + 8)  = v2;
                *(float4*)(dst + 12) = v3;
            }
            __syncthreads();
            for (int k = 0; k < 64; k++) {
                float4 v = *(const float4*)&Vh[k * 68 + tx * 4];
#pragma unroll
                for (int i = 0; i < 4; i++) {
                    float p = Ps[(ty * 4 + i) * 68 + k];
                    o[i][hf * 4 + 0] = fmaf(p, v.x, o[i][hf * 4 + 0]);
                    o[i][hf * 4 + 1] = fmaf(p, v.y, o[i][hf * 4 + 1]);
                    o[i][hf * 4 + 2] = fmaf(p, v.z, o[i][hf * 4 + 2]);
                    o[i][hf * 4 + 3] = fmaf(p, v.w, o[i][hf * 4 + 3]);
                }
            }
            __syncthreads();
        }
    }

#pragma unroll
    for (int i = 0; i < 4; i++) {
        float inv = 1.f / l[i];
        int gr = i0 * 64 + ty * 4 + i;
        float* dst = g_attn + (((size_t)(b * H_ + h) * T_ + gr) * D_);
        float4 o0 = {o[i][0] * inv, o[i][1] * inv, o[i][2] * inv, o[i][3] * inv};
        float4 o1 = {o[i][4] * inv, o[i][5] * inv, o[i][6] * inv, o[i][7] * inv};
        *(float4*)(dst + tx * 4)      = o0;
        *(float4*)(dst + 64 + tx * 4) = o1;
    }
}

// ---------------- launch ----------------
extern "C" void kernel_launch(void* const* d_in, const int* in_sizes, int n_in,
                              void* d_out, int out_size)
{
    const float* x    = (const float*)d_in[0];
    const float* Wqkv = (const float*)d_in[1];
    const float* Wout = (const float*)d_in[2];
    float* out = (float*)d_out;

    float *qkv = nullptr, *attn = nullptr;
    cudaGetSymbolAddress((void**)&qkv,  g_qkv);
    cudaGetSymbolAddress((void**)&attn, g_attn);

    cudaFuncSetAttribute(mma_gemm, cudaFuncAttributeMaxDynamicSharedMemorySize, 131072);

    // 1) QKV projection: [4096,2048] @ [2048,6144]
    mma_gemm<<<dim3(N1_ / 128, M_ / 128), 256, 131072>>>(x, Wqkv, qkv, M_, N1_, C_);
    // 2) RoPE tables + apply
    rope_table_kernel<<<(T_ * HALF_ + 255) / 256, 256>>>();
    rope_apply_kernel<<<(B_ * T_ * H_ * HALF_) / 256, 256>>>();
    // 3) causal flash attention
    flash_kernel<<<dim3(T_ / 64, B_ * H_), 256>>>();
    // 4) output projection: [4096,2048] @ [2048,2048]
    mma_gemm<<<dim3(C_ / 128, M_ / 128), 256, 131072>>>(attn, Wout, out, M_, C_, C_);
}

// round 3
// speedup vs baseline: 2.5789x; 1.4714x over previous
#include <cuda_runtime.h>
#include <cuda_bf16.h>
#include <cstdint>
#include <math.h>

#define B_   2
#define T_   2048
#define C_   2048
#define H_   16
#define D_   128
#define HALF_ 64
#define M_   (B_*T_)       // 4096 rows
#define N1_  (3*C_)        // 6144
#define RS_  (3*C_)        // qkv row stride
#define BH_  (B_*H_)       // 32

// ---------------- scratch (device globals; no cudaMalloc allowed) ----------------
__device__ float g_qkv[(size_t)M_ * N1_];            // [B*T, 3*C]
__device__ float g_attn[(size_t)M_ * C_];            // flat (B,H,T,D)
__device__ float g_sin[T_ * HALF_];
__device__ float g_cos[T_ * HALF_];
__device__ __nv_bfloat16 g_qh[(size_t)BH_ * T_ * D_];  // scaled+roped Q hi
__device__ __nv_bfloat16 g_ql[(size_t)BH_ * T_ * D_];
__device__ __nv_bfloat16 g_kh[(size_t)BH_ * T_ * D_];
__device__ __nv_bfloat16 g_kl[(size_t)BH_ * T_ * D_];
__device__ __nv_bfloat16 g_vh[(size_t)BH_ * T_ * D_];
__device__ __nv_bfloat16 g_vl[(size_t)BH_ * T_ * D_];

// ---------------- fast exp (FFMA-pipe) --------------
__device__ __forceinline__ float fast_exp(float x) {
    x = fmaxf(x, -87.0f);
    float t = x * 1.4426950408889634f;
    int   i = __float2int_rn(t);
    float f = t - (float)i;
    float p =          1.3333558146428443e-3f;
    p = fmaf(p, f, 9.6181291780723730e-3f);
    p = fmaf(p, f, 5.5504108664821580e-2f);
    p = fmaf(p, f, 2.4022650695910072e-1f);
    p = fmaf(p, f, 6.9314718055994531e-1f);
    p = fmaf(p, f, 1.0f);
    return __int_as_float((i + 127) << 23) * p;
}

// ---------------- MMA / LDSM primitives ----------------
#define LDSM_X4(R0,R1,R2,R3,ADDR) \
    asm volatile("ldmatrix.sync.aligned.m8n8.x4.shared.b16 {%0,%1,%2,%3}, [%4];" \
                 : "=r"(R0), "=r"(R1), "=r"(R2), "=r"(R3) : "r"(ADDR))
#define LDSM_X4_T(R0,R1,R2,R3,ADDR) \
    asm volatile("ldmatrix.sync.aligned.m8n8.x4.trans.shared.b16 {%0,%1,%2,%3}, [%4];" \
                 : "=r"(R0), "=r"(R1), "=r"(R2), "=r"(R3) : "r"(ADDR))

__device__ __forceinline__ void mma16816(float* d, const unsigned* a, const unsigned* b) {
    asm volatile(
        "mma.sync.aligned.m16n8k16.row.col.f32.bf16.bf16.f32 "
        "{%0,%1,%2,%3}, {%4,%5,%6,%7}, {%8,%9}, {%0,%1,%2,%3};"
        : "+f"(d[0]), "+f"(d[1]), "+f"(d[2]), "+f"(d[3])
        : "r"(a[0]), "r"(a[1]), "r"(a[2]), "r"(a[3]), "r"(b[0]), "r"(b[1]));
}

// split fp32 pair -> packed bf16x2 hi and lo
__device__ __forceinline__ void split2(float x, float y, unsigned& hi, unsigned& lo) {
    __nv_bfloat162 h2 = __floats2bfloat162_rn(x, y);
    float hx = __bfloat162float(h2.x);
    float hy = __bfloat162float(h2.y);
    __nv_bfloat162 l2 = __floats2bfloat162_rn(x - hx, y - hy);
    hi = *reinterpret_cast<unsigned*>(&h2);
    lo = *reinterpret_cast<unsigned*>(&l2);
}

// =================================================================================
//  bf16x3 split-precision tensor-core GEMM (unchanged from round 2)
// =================================================================================
#define S_ALO 16384
#define S_BHI 32768
#define S_BLO 49152
#define STAGE_ 65536

__device__ __forceinline__ void load_stage(const float* ap, const float* bp,
                                           int K, int N, uint4* sa, uint4* sb) {
#pragma unroll
    for (int i = 0; i < 4; i++) {
        const uint4* p = (const uint4*)(ap + (size_t)(32 * i) * K);
        sa[2 * i]     = p[0];
        sa[2 * i + 1] = p[1];
        const uint4* q = (const uint4*)(bp + (size_t)(16 * i) * N);
        sb[2 * i]     = q[0];
        sb[2 * i + 1] = q[1];
    }
}

__device__ __forceinline__ void store_stage(char* s, const uint4* sa, const uint4* sb,
                                            int aoff, int boff) {
#pragma unroll
    for (int i = 0; i < 4; i++) {
        const float* f = (const float*)&sa[2 * i];
        unsigned h[4], l[4];
#pragma unroll
        for (int j = 0; j < 4; j++) split2(f[2 * j], f[2 * j + 1], h[j], l[j]);
        *(uint4*)(s + aoff + i * 4096)          = make_uint4(h[0], h[1], h[2], h[3]);
        *(uint4*)(s + S_ALO + aoff + i * 4096)  = make_uint4(l[0], l[1], l[2], l[3]);
        const float* g = (const float*)&sb[2 * i];
#pragma unroll
        for (int j = 0; j < 4; j++) split2(g[2 * j], g[2 * j + 1], h[j], l[j]);
        *(uint4*)(s + S_BHI + boff + i * 4096)  = make_uint4(h[0], h[1], h[2], h[3]);
        *(uint4*)(s + S_BLO + boff + i * 4096)  = make_uint4(l[0], l[1], l[2], l[3]);
    }
}

__global__ void __launch_bounds__(256) mma_gemm(const float* __restrict__ A,
                                                const float* __restrict__ B,
                                                float* __restrict__ C,
                                                int M, int N, int K)
{
    extern __shared__ char smem[];
    const uint32_t smem_u32 = (uint32_t)__cvta_generic_to_shared(smem);

    const int tid  = threadIdx.x;
    const int lane = tid & 31;
    const int wid  = tid >> 5;
    const int warp_m = wid & 1;
    const int warp_n = wid >> 1;
    const int quad = lane >> 3;
    const int rq   = lane & 7;

    const int bm = blockIdx.y * 128;
    const int bn = blockIdx.x * 128;

    const int rA  = tid >> 3;
    const int kbA = tid & 7;
    const int kB  = tid >> 4;
    const int nbB = tid & 15;

    const float* Aq = A + (size_t)(bm + rA) * K + kbA * 8;
    const float* Bq = B + (size_t)kB * N + bn + nbB * 8;

    const int aoff = rA * 128 + (kbA ^ (rA & 7)) * 16;
    const int boff = kB * 256 + (((nbB & 8) | ((nbB & 7) ^ (kB & 7)))) * 16;

    const int aRowL = warp_m * 64 + (quad & 1) * 8 + rq;
    const int kHalf = quad >> 1;
    const int arow7 = aRowL & 7;
    const int arowByte = aRowL * 128;

    const int kL = (quad & 1) * 8 + rq;
    int nbswp[2];
#pragma unroll
    for (int p = 0; p < 2; p++) {
        int nb = warp_n * 4 + (quad >> 1) + p * 2;
        nbswp[p] = (nb & 8) | ((nb & 7) ^ (kL & 7));
    }
    const int bByteBase = kL * 256;

    float acc[4][4][4];
#pragma unroll
    for (int mt = 0; mt < 4; mt++)
#pragma unroll
        for (int nt = 0; nt < 4; nt++)
#pragma unroll
            for (int c = 0; c < 4; c++) acc[mt][nt][c] = 0.f;

    uint4 sa[8], sb[8];
    load_stage(Aq, Bq, K, N, sa, sb);
    store_stage(smem, sa, sb, aoff, boff);
    __syncthreads();

    const int KT = K >> 6;
    int buf = 0;
    for (int kt = 0; kt < KT; kt++) {
        const bool more = (kt + 1 < KT);
        if (more)
            load_stage(Aq + (kt + 1) * 64, Bq + (size_t)(kt + 1) * 64 * N, K, N, sa, sb);

        const uint32_t sbase = smem_u32 + buf * STAGE_;
#pragma unroll
        for (int kk = 0; kk < 4; kk++) {
            unsigned ah[4][4], al[4][4], bh[2][4], bl[2][4];
            const int asw = ((2 * kk + kHalf) ^ arow7) * 16;
#pragma unroll
            for (int mt = 0; mt < 4; mt++) {
                uint32_t ad = sbase + arowByte + mt * 2048 + asw;
                LDSM_X4(ah[mt][0], ah[mt][1], ah[mt][2], ah[mt][3], ad);
                LDSM_X4(al[mt][0], al[mt][1], al[mt][2], al[mt][3], ad + S_ALO);
            }
#pragma unroll
            for (int p = 0; p < 2; p++) {
                uint32_t bd = sbase + kk * 4096 + bByteBase + nbswp[p] * 16;
                LDSM_X4_T(bh[p][0], bh[p][1], bh[p][2], bh[p][3], bd + S_BHI);
                LDSM_X4_T(bl[p][0], bl[p][1], bl[p][2], bl[p][3], bd + S_BLO);
            }
#pragma unroll
            for (int mt = 0; mt < 4; mt++)
#pragma unroll
                for (int nt = 0; nt < 4; nt++) {
                    const unsigned* bph = &bh[nt >> 1][(nt & 1) * 2];
                    const unsigned* bpl = &bl[nt >> 1][(nt & 1) * 2];
                    mma16816(acc[mt][nt], ah[mt], bph);
                    mma16816(acc[mt][nt], al[mt], bph);
                    mma16816(acc[mt][nt], ah[mt], bpl);
                }
        }

        if (more) store_stage(smem + (buf ^ 1) * STAGE_, sa, sb, aoff, boff);
        __syncthreads();
        buf ^= 1;
    }

    const int r0 = bm + warp_m * 64 + (lane >> 2);
    const int c0 = bn + warp_n * 32 + (lane & 3) * 2;
#pragma unroll
    for (int mt = 0; mt < 4; mt++)
#pragma unroll
        for (int nt = 0; nt < 4; nt++) {
            float* p0 = C + (size_t)(r0 + mt * 16) * N + c0 + nt * 8;
            float* p1 = C + (size_t)(r0 + mt * 16 + 8) * N + c0 + nt * 8;
            *(float2*)p0 = make_float2(acc[mt][nt][0], acc[mt][nt][1]);
            *(float2*)p1 = make_float2(acc[mt][nt][2], acc[mt][nt][3]);
        }
}

// ---------------- RoPE tables (fp64 angles) ------
__global__ void rope_table_kernel()
{
    int idx = blockIdx.x * blockDim.x + threadIdx.x;
    if (idx >= T_ * HALF_) return;
    int t = idx / HALF_, j = idx % HALF_;
    double div  = exp(-(double)(2 * j) * 9.210340371976184 / 128.0);
    float  divf = (float)div;
    float  angf = (float)t * divf;
    g_sin[idx] = (float)sin((double)angf);
    g_cos[idx] = (float)cos((double)angf);
}

// ---------------- fused RoPE + scale + bf16 hi/lo split, head-major layout -------
__device__ __forceinline__ void splitw(float x, __nv_bfloat16* hi, __nv_bfloat16* lo, size_t i) {
    __nv_bfloat16 h = __float2bfloat16(x);
    hi[i] = h;
    lo[i] = __float2bfloat16(x - __bfloat162float(h));
}

__global__ void convert_kernel()
{
    int idx = blockIdx.x * blockDim.x + threadIdx.x;   // ((b*T+t)*H + h)*64 + j
    int j  = idx & 63;
    int h  = (idx >> 6) & (H_ - 1);
    int bt = idx >> 10;
    int t  = bt & (T_ - 1);
    int b  = bt >> 11;

    float sn = g_sin[t * HALF_ + j];
    float cs = g_cos[t * HALF_ + j];
    const float scale = 0.088388347648318447f;   // 1/sqrt(128)

    size_t src = (size_t)bt * RS_ + h * D_;
    float q1 = g_qkv[src + j],          q2 = g_qkv[src + j + HALF_];
    float k1 = g_qkv[src + C_ + j],     k2 = g_qkv[src + C_ + j + HALF_];
    float v1 = g_qkv[src + 2*C_ + j],   v2 = g_qkv[src + 2*C_ + j + HALF_];

    float qa = (q1 * cs - q2 * sn) * scale;
    float qb = (q2 * cs + q1 * sn) * scale;
    float ka = k1 * cs - k2 * sn;
    float kb = k2 * cs + k1 * sn;

    size_t dst = ((size_t)(b * H_ + h) * T_ + t) * D_;
    splitw(qa, g_qh, g_ql, dst + j);
    splitw(qb, g_qh, g_ql, dst + j + HALF_);
    splitw(ka, g_kh, g_kl, dst + j);
    splitw(kb, g_kh, g_kl, dst + j + HALF_);
    splitw(v1, g_vh, g_vl, dst + j);
    splitw(v2, g_vh, g_vl, dst + j + HALF_);
}

// =================================================================================
//  Tensor-core causal flash attention: 128 q-rows x 64 keys/iter, bf16x3 both GEMMs
// =================================================================================
#define FSM_QH 0
#define FSM_QL 32768
#define FSM_KH 65536
#define FSM_KL 81920
#define FSM_VH 98304
#define FSM_VL 114688
#define FSM_TOTAL 131072

__device__ __forceinline__ uint32_t fsw(int r, int c) {   // row, 16B-chunk -> byte offset
    return (uint32_t)(r * 256 + ((((c ^ r) & 7) | (c & 8)) << 4));
}

__global__ void __launch_bounds__(256) flash_mma_kernel()
{
    extern __shared__ char fsm[];
    const uint32_t sb = (uint32_t)__cvta_generic_to_shared(fsm);

    const int i0  = (gridDim.x - 1) - blockIdx.x;   // heavy tiles first
    const int bh  = blockIdx.y;
    const int tid = threadIdx.x;
    const int lane = tid & 31;
    const int w    = tid >> 5;
    const int quad = lane >> 3;
    const int rq   = lane & 7;
    const int lr   = lane >> 2;
    const int lq   = lane & 3;

    const size_t kvbase   = (size_t)bh * (T_ * D_);
    const size_t qrowbase = kvbase + (size_t)i0 * 128 * D_;

    // ---- load Q hi/lo tiles (128x128 bf16 each) ----
    {
        int r  = tid >> 1;
        int cb = (tid & 1) * 8;
        const size_t g = qrowbase + (size_t)r * D_;
#pragma unroll
        for (int j = 0; j < 8; j++) {
            int c = cb + j;
            uint32_t sw = fsw(r, c);
            *(uint4*)(fsm + FSM_QH + sw) = *(const uint4*)(g_qh + g + c * 8);
            *(uint4*)(fsm + FSM_QL + sw) = *(const uint4*)(g_ql + g + c * 8);
        }
    }

    float o[16][4];
#pragma unroll
    for (int dt = 0; dt < 16; dt++)
#pragma unroll
        for (int e = 0; e < 4; e++) o[dt][e] = 0.f;
    float mcur[2] = {-3.4e38f, -3.4e38f};
    float lcur[2] = {0.f, 0.f};

    const int arow  = 16 * w + (quad & 1) * 8 + rq;   // A ldmatrix row (Q / within 128)
    const int rB    = (quad & 1) * 8 + rq;            // B ldmatrix row base
    const int cHalf = quad >> 1;

    const int jmax = 2 * i0 + 1;
    for (int j0 = 0; j0 <= jmax; j0++) {
        __syncthreads();
        // ---- load K/V hi/lo tiles (64x128 bf16 each) ----
        {
            int r  = tid >> 2;
            int cb = (tid & 3) * 4;
            const size_t g = kvbase + (size_t)(j0 * 64 + r) * D_;
#pragma unroll
            for (int j = 0; j < 4; j++) {
                int c = cb + j;
                uint32_t sw = fsw(r, c);
                *(uint4*)(fsm + FSM_KH + sw) = *(const uint4*)(g_kh + g + c * 8);
                *(uint4*)(fsm + FSM_KL + sw) = *(const uint4*)(g_kl + g + c * 8);
                *(uint4*)(fsm + FSM_VH + sw) = *(const uint4*)(g_vh + g + c * 8);
                *(uint4*)(fsm + FSM_VL + sw) = *(const uint4*)(g_vl + g + c * 8);
            }
        }
        __syncthreads();

        // ---- S = Q K^T (scaled already), 8 k-steps over d ----
        float s[8][4];
#pragma unroll
        for (int nt = 0; nt < 8; nt++)
#pragma unroll
            for (int e = 0; e < 4; e++) s[nt][e] = 0.f;

#pragma unroll
        for (int kk = 0; kk < 8; kk++) {
            const int ca = 2 * kk + cHalf;
            unsigned ah[4], al[4];
            uint32_t aaddr = sb + fsw(arow, ca);
            LDSM_X4(ah[0], ah[1], ah[2], ah[3], aaddr + FSM_QH);
            LDSM_X4(al[0], al[1], al[2], al[3], aaddr + FSM_QL);
            unsigned kh4[4][4], kl4[4][4];
#pragma unroll
            for (int p = 0; p < 4; p++) {
                uint32_t kaddr = sb + fsw(16 * p + rB, ca);
                LDSM_X4(kh4[p][0], kh4[p][1], kh4[p][2], kh4[p][3], kaddr + FSM_KH);
                LDSM_X4(kl4[p][0], kl4[p][1], kl4[p][2], kl4[p][3], kaddr + FSM_KL);
            }
#pragma unroll
            for (int p = 0; p < 4; p++) {
                unsigned bh0[2] = {kh4[p][0], kh4[p][2]};
                unsigned bh1[2] = {kh4[p][1], kh4[p][3]};
                unsigned bl0[2] = {kl4[p][0], kl4[p][2]};
                unsigned bl1[2] = {kl4[p][1], kl4[p][3]};
                mma16816(s[2*p],   ah, bh0);
                mma16816(s[2*p],   al, bh0);
                mma16816(s[2*p],   ah, bl0);
                mma16816(s[2*p+1], ah, bh1);
                mma16816(s[2*p+1], al, bh1);
                mma16816(s[2*p+1], ah, bl1);
            }
        }

        // ---- causal mask (only diagonal-straddling tiles) ----
        if (j0 >= 2 * i0) {
            const int qr0 = i0 * 128 + 16 * w + lr;
            const int kc0 = j0 * 64 + 2 * lq;
#pragma unroll
            for (int nt = 0; nt < 8; nt++)
#pragma unroll
                for (int e = 0; e < 4; e++) {
                    int r = qr0 + (e >> 1) * 8;
                    int c = kc0 + 8 * nt + (e & 1);
                    if (c > r) s[nt][e] = -3.4e38f;
                }
        }

        // ---- online softmax (2 rows per thread) ----
#pragma unroll
        for (int z = 0; z < 2; z++) {
            float mx = -3.4e38f;
#pragma unroll
            for (int nt = 0; nt < 8; nt++)
                mx = fmaxf(mx, fmaxf(s[nt][2*z], s[nt][2*z+1]));
            mx = fmaxf(mx, __shfl_xor_sync(0xffffffffu, mx, 1));
            mx = fmaxf(mx, __shfl_xor_sync(0xffffffffu, mx, 2));
            float mn = fmaxf(mcur[z], mx);
            float alpha = fast_exp(mcur[z] - mn);
            float ls = 0.f;
#pragma unroll
            for (int nt = 0; nt < 8; nt++) {
                float p0 = fast_exp(s[nt][2*z]   - mn);
                float p1 = fast_exp(s[nt][2*z+1] - mn);
                s[nt][2*z] = p0; s[nt][2*z+1] = p1;
                ls += p0 + p1;
            }
            ls += __shfl_xor_sync(0xffffffffu, ls, 1);
            ls += __shfl_xor_sync(0xffffffffu, ls, 2);
            lcur[z] = lcur[z] * alpha + ls;
            mcur[z] = mn;
#pragma unroll
            for (int dt = 0; dt < 16; dt++) {
                o[dt][2*z]   *= alpha;
                o[dt][2*z+1] *= alpha;
            }
        }

        // ---- pack P into A-fragments (hi/lo) directly from registers ----
        unsigned ph[4][4], pl[4][4];
#pragma unroll
        for (int kk2 = 0; kk2 < 4; kk2++) {
            split2(s[2*kk2][0],   s[2*kk2][1],   ph[kk2][0], pl[kk2][0]);
            split2(s[2*kk2][2],   s[2*kk2][3],   ph[kk2][1], pl[kk2][1]);
            split2(s[2*kk2+1][0], s[2*kk2+1][1], ph[kk2][2], pl[kk2][2]);
            split2(s[2*kk2+1][2], s[2*kk2+1][3], ph[kk2][3], pl[kk2][3]);
        }

        // ---- O += P V, 4 k-steps over s ----
#pragma unroll
        for (int kk2 = 0; kk2 < 4; kk2++) {
            const int rV = 16 * kk2 + rB;
#pragma unroll
            for (int p = 0; p < 8; p++) {
                unsigned vh4[4], vl4[4];
                uint32_t vaddr = sb + fsw(rV, 2 * p + cHalf);
                LDSM_X4_T(vh4[0], vh4[1], vh4[2], vh4[3], vaddr + FSM_VH);
                LDSM_X4_T(vl4[0], vl4[1], vl4[2], vl4[3], vaddr + FSM_VL);
                mma16816(o[2*p],   ph[kk2], &vh4[0]);
                mma16816(o[2*p],   pl[kk2], &vh4[0]);
                mma16816(o[2*p],   ph[kk2], &vl4[0]);
                mma16816(o[2*p+1], ph[kk2], &vh4[2]);
                mma16816(o[2*p+1], pl[kk2], &vh4[2]);
                mma16816(o[2*p+1], ph[kk2], &vl4[2]);
            }
        }
    }

    // ---- epilogue: O /= l, write flat (B,H,T,D) fp32 ----
    const float inv0 = 1.f / lcur[0];
    const float inv1 = 1.f / lcur[1];
    const size_t obase = ((size_t)bh * T_ + (size_t)i0 * 128 + 16 * w + lr) * D_;
#pragma unroll
    for (int dt = 0; dt < 16; dt++) {
        int col = 8 * dt + 2 * lq;
        *(float2*)(g_attn + obase + col)          = make_float2(o[dt][0] * inv0, o[dt][1] * inv0);
        *(float2*)(g_attn + obase + 8 * D_ + col) = make_float2(o[dt][2] * inv1, o[dt][3] * inv1);
    }
}

// ---------------- launch ----------------
extern "C" void kernel_launch(void* const* d_in, const int* in_sizes, int n_in,
                              void* d_out, int out_size)
{
    const float* x    = (const float*)d_in[0];
    const float* Wqkv = (const float*)d_in[1];
    const float* Wout = (const float*)d_in[2];
    float* out = (float*)d_out;

    float *qkv = nullptr, *attn = nullptr;
    cudaGetSymbolAddress((void**)&qkv,  g_qkv);
    cudaGetSymbolAddress((void**)&attn, g_attn);

    cudaFuncSetAttribute(mma_gemm, cudaFuncAttributeMaxDynamicSharedMemorySize, 131072);
    cudaFuncSetAttribute(flash_mma_kernel, cudaFuncAttributeMaxDynamicSharedMemorySize, FSM_TOTAL);

    // 1) QKV projection
    mma_gemm<<<dim3(N1_ / 128, M_ / 128), 256, 131072>>>(x, Wqkv, qkv, M_, N1_, C_);
    // 2) RoPE tables + fused rope/scale/split/transpose
    rope_table_kernel<<<(T_ * HALF_ + 255) / 256, 256>>>();
    convert_kernel<<<(B_ * T_ * H_ * HALF_) / 256, 256>>>();
    // 3) tensor-core causal flash attention
    flash_mma_kernel<<<dim3(T_ / 128, BH_), 256, FSM_TOTAL>>>();
    // 4) output projection
    mma_gemm<<<dim3(C_ / 128, M_ / 128), 256, 131072>>>(attn, Wout, out, M_, C_, C_);
}

// round 5
// speedup vs baseline: 2.8031x; 1.0869x over previous
#include <cuda_runtime.h>
#include <cuda_bf16.h>
#include <cstdint>
#include <math.h>

#define B_   2
#define T_   2048
#define C_   2048
#define H_   16
#define D_   128
#define HALF_ 64
#define M_   (B_*T_)       // 4096
#define N1_  (3*C_)        // 6144
#define RS_  (3*C_)
#define BH_  (B_*H_)       // 32

// ---------------- scratch (device globals) ----------------
__device__ float g_qkv[(size_t)M_ * N1_];              // [B*T, 3*C] fp32 (GEMM1 out)
__device__ float g_sin[T_ * HALF_];
__device__ float g_cos[T_ * HALF_];
__device__ __nv_bfloat16 g_qh[(size_t)BH_ * T_ * D_];  // roped+scaled Q hi/lo, head-major
__device__ __nv_bfloat16 g_ql[(size_t)BH_ * T_ * D_];
__device__ __nv_bfloat16 g_kh[(size_t)BH_ * T_ * D_];
__device__ __nv_bfloat16 g_kl[(size_t)BH_ * T_ * D_];
__device__ __nv_bfloat16 g_vh[(size_t)BH_ * T_ * D_];
__device__ __nv_bfloat16 g_vl[(size_t)BH_ * T_ * D_];
__device__ __nv_bfloat16 g_xh[(size_t)M_ * C_];        // x split [M][K]
__device__ __nv_bfloat16 g_xl[(size_t)M_ * C_];
__device__ __nv_bfloat16 g_w1h[(size_t)C_ * N1_];      // Wqkv split [K][N] (no transpose)
__device__ __nv_bfloat16 g_w1l[(size_t)C_ * N1_];
__device__ __nv_bfloat16 g_w2h[(size_t)C_ * C_];       // Wout split [K][N]
__device__ __nv_bfloat16 g_w2l[(size_t)C_ * C_];
__device__ __nv_bfloat16 g_oh[(size_t)M_ * C_];        // attention out split (flat B,H,T,D)
__device__ __nv_bfloat16 g_ol[(size_t)M_ * C_];

// ---------------- fast exp (FFMA-pipe) --------------
__device__ __forceinline__ float fast_exp(float x) {
    x = fmaxf(x, -87.0f);
    float t = x * 1.4426950408889634f;
    int   i = __float2int_rn(t);
    float f = t - (float)i;
    float p =          1.3333558146428443e-3f;
    p = fmaf(p, f, 9.6181291780723730e-3f);
    p = fmaf(p, f, 5.5504108664821580e-2f);
    p = fmaf(p, f, 2.4022650695910072e-1f);
    p = fmaf(p, f, 6.9314718055994531e-1f);
    p = fmaf(p, f, 1.0f);
    return __int_as_float((i + 127) << 23) * p;
}

// ---------------- MMA / LDSM / cp.async primitives ----------------
#define LDSM_X4(R0,R1,R2,R3,ADDR) \
    asm volatile("ldmatrix.sync.aligned.m8n8.x4.shared.b16 {%0,%1,%2,%3}, [%4];" \
                 : "=r"(R0), "=r"(R1), "=r"(R2), "=r"(R3) : "r"(ADDR))
#define LDSM_X4_T(R0,R1,R2,R3,ADDR) \
    asm volatile("ldmatrix.sync.aligned.m8n8.x4.trans.shared.b16 {%0,%1,%2,%3}, [%4];" \
                 : "=r"(R0), "=r"(R1), "=r"(R2), "=r"(R3) : "r"(ADDR))
#define CP16(DST, SRC) \
    asm volatile("cp.async.cg.shared.global [%0], [%1], 16;" :: "r"(DST), "l"(SRC))
#define CP_COMMIT() asm volatile("cp.async.commit_group;" ::: "memory")
#define CP_WAIT0()  asm volatile("cp.async.wait_group 0;" ::: "memory")

__device__ __forceinline__ void mma16816(float* d, const unsigned* a, const unsigned* b) {
    asm volatile(
        "mma.sync.aligned.m16n8k16.row.col.f32.bf16.bf16.f32 "
        "{%0,%1,%2,%3}, {%4,%5,%6,%7}, {%8,%9}, {%0,%1,%2,%3};"
        : "+f"(d[0]), "+f"(d[1]), "+f"(d[2]), "+f"(d[3])
        : "r"(a[0]), "r"(a[1]), "r"(a[2]), "r"(a[3]), "r"(b[0]), "r"(b[1]));
}

__device__ __forceinline__ void split2(float x, float y, unsigned& hi, unsigned& lo) {
    __nv_bfloat162 h2 = __floats2bfloat162_rn(x, y);
    float hx = __bfloat162float(h2.x);
    float hy = __bfloat162float(h2.y);
    __nv_bfloat162 l2 = __floats2bfloat162_rn(x - hx, y - hy);
    hi = *reinterpret_cast<unsigned*>(&h2);
    lo = *reinterpret_cast<unsigned*>(&l2);
}

// ---------------- pre-pass: elementwise fp32 -> bf16 hi/lo split (vectorized) ----
__global__ void split_kernel(const float* __restrict__ src,
                             __nv_bfloat16* __restrict__ th,
                             __nv_bfloat16* __restrict__ tl)
{
    size_t i = ((size_t)blockIdx.x * blockDim.x + threadIdx.x) * 4;
    float4 v = *(const float4*)(src + i);
    unsigned h0, l0, h1, l1;
    split2(v.x, v.y, h0, l0);
    split2(v.z, v.w, h1, l1);
    *(uint2*)(th + i) = make_uint2(h0, h1);
    *(uint2*)(tl + i) = make_uint2(l0, l1);
}

// =================================================================================
//  bf16x3 split-precision tensor-core GEMM, pre-split inputs:
//  C[M,N] = (Ah+Al)[M,K] @ (Bh+Bl)[K,N], 128x128x64 stages, 256 thr, mma.m16n8k16
// =================================================================================
#define S_ALO 16384
#define S_BHI 32768
#define S_BLO 49152
#define STAGE_ 65536

__global__ void __launch_bounds__(256) mma_gemm(const __nv_bfloat16* __restrict__ Ah,
                                                const __nv_bfloat16* __restrict__ Al,
                                                const __nv_bfloat16* __restrict__ Bh,
                                                const __nv_bfloat16* __restrict__ Bl,
                                                float* __restrict__ C,
                                                int M, int N, int K)
{
    extern __shared__ char smem[];
    const uint32_t smem_u32 = (uint32_t)__cvta_generic_to_shared(smem);

    const int tid  = threadIdx.x;
    const int lane = tid & 31;
    const int wid  = tid >> 5;
    const int warp_m = wid & 1;
    const int warp_n = wid >> 1;
    const int quad = lane >> 3;
    const int rq   = lane & 7;

    const int bm = blockIdx.y * 128;
    const int bn = blockIdx.x * 128;

    // staging: A tile 128r x 8 chunks, B tile 64r x 16 chunks, 4 chunks/thread each
    int swA[4], swB[4];
    size_t offA[4], offB[4];
#pragma unroll
    for (int i = 0; i < 4; i++) {
        int ia = i * 256 + tid;
        int ra = ia >> 3, ca = ia & 7;
        swA[i]  = ra * 128 + ((ca ^ (ra & 7)) << 4);
        offA[i] = (size_t)(bm + ra) * K + ca * 8;
        int ib = i * 256 + tid;
        int rb = ib >> 4, cb = ib & 15;
        swB[i]  = rb * 256 + (((cb & 8) | ((cb & 7) ^ (rb & 7))) << 4);
        offB[i] = (size_t)rb * N + bn + cb * 8;
    }

    // ldmatrix lane addressing (same smem layout as before)
    const int aRowL = warp_m * 64 + (quad & 1) * 8 + rq;
    const int kHalf = quad >> 1;
    const int arow7 = aRowL & 7;
    const int arowByte = aRowL * 128;

    const int kL = (quad & 1) * 8 + rq;
    int nbswp[2];
#pragma unroll
    for (int p = 0; p < 2; p++) {
        int nb = warp_n * 4 + (quad >> 1) + p * 2;
        nbswp[p] = (nb & 8) | ((nb & 7) ^ (kL & 7));
    }
    const int bByteBase = kL * 256;

    float acc[4][4][4];
#pragma unroll
    for (int mt = 0; mt < 4; mt++)
#pragma unroll
        for (int nt = 0; nt < 4; nt++)
#pragma unroll
            for (int c = 0; c < 4; c++) acc[mt][nt][c] = 0.f;

    uint4 rah[4], ral[4], rbh[4], rbl[4];

#define G_LOAD(k0) do { \
    _Pragma("unroll") for (int i = 0; i < 4; i++) { \
        rah[i] = *(const uint4*)(Ah + offA[i] + (k0)); \
        ral[i] = *(const uint4*)(Al + offA[i] + (k0)); \
        rbh[i] = *(const uint4*)(Bh + offB[i] + (size_t)(k0) * N); \
        rbl[i] = *(const uint4*)(Bl + offB[i] + (size_t)(k0) * N); } } while (0)

#define G_STS(buf) do { \
    char* p_ = smem + (buf) * STAGE_; \
    _Pragma("unroll") for (int i = 0; i < 4; i++) { \
        *(uint4*)(p_ + swA[i])          = rah[i]; \
        *(uint4*)(p_ + S_ALO + swA[i])  = ral[i]; \
        *(uint4*)(p_ + S_BHI + swB[i])  = rbh[i]; \
        *(uint4*)(p_ + S_BLO + swB[i])  = rbl[i]; } } while (0)

    G_LOAD(0);
    G_STS(0);
    __syncthreads();

    const int KT = K >> 6;
    int buf = 0;
    for (int kt = 0; kt < KT; kt++) {
        const bool more = (kt + 1 < KT);
        if (more) G_LOAD((kt + 1) * 64);

        const uint32_t sbase = smem_u32 + buf * STAGE_;
#pragma unroll
        for (int kk = 0; kk < 4; kk++) {
            unsigned ah[4][4], al[4][4], bh[2][4], bl[2][4];
            const int asw = ((2 * kk + kHalf) ^ arow7) * 16;
#pragma unroll
            for (int mt = 0; mt < 4; mt++) {
                uint32_t ad = sbase + arowByte + mt * 2048 + asw;
                LDSM_X4(ah[mt][0], ah[mt][1], ah[mt][2], ah[mt][3], ad);
                LDSM_X4(al[mt][0], al[mt][1], al[mt][2], al[mt][3], ad + S_ALO);
            }
#pragma unroll
            for (int p = 0; p < 2; p++) {
                uint32_t bd = sbase + kk * 4096 + bByteBase + nbswp[p] * 16;
                LDSM_X4_T(bh[p][0], bh[p][1], bh[p][2], bh[p][3], bd + S_BHI);
                LDSM_X4_T(bl[p][0], bl[p][1], bl[p][2], bl[p][3], bd + S_BLO);
            }
#pragma unroll
            for (int mt = 0; mt < 4; mt++)
#pragma unroll
                for (int nt = 0; nt < 4; nt++) {
                    const unsigned* bph = &bh[nt >> 1][(nt & 1) * 2];
                    const unsigned* bpl = &bl[nt >> 1][(nt & 1) * 2];
                    mma16816(acc[mt][nt], ah[mt], bph);
                    mma16816(acc[mt][nt], al[mt], bph);
                    mma16816(acc[mt][nt], ah[mt], bpl);
                }
        }

        if (more) G_STS(buf ^ 1);
        __syncthreads();
        buf ^= 1;
    }
#undef G_LOAD
#undef G_STS

    const int r0 = bm + warp_m * 64 + (lane >> 2);
    const int c0 = bn + warp_n * 32 + (lane & 3) * 2;
#pragma unroll
    for (int mt = 0; mt < 4; mt++)
#pragma unroll
        for (int nt = 0; nt < 4; nt++) {
            float* p0 = C + (size_t)(r0 + mt * 16) * N + c0 + nt * 8;
            float* p1 = C + (size_t)(r0 + mt * 16 + 8) * N + c0 + nt * 8;
            *(float2*)p0 = make_float2(acc[mt][nt][0], acc[mt][nt][1]);
            *(float2*)p1 = make_float2(acc[mt][nt][2], acc[mt][nt][3]);
        }
}

// ---------------- RoPE tables (fp64 angles) ------
__global__ void rope_table_kernel()
{
    int idx = blockIdx.x * blockDim.x + threadIdx.x;
    if (idx >= T_ * HALF_) return;
    int t = idx / HALF_, j = idx % HALF_;
    double div  = exp(-(double)(2 * j) * 9.210340371976184 / 128.0);
    float  divf = (float)div;
    float  angf = (float)t * divf;
    g_sin[idx] = (float)sin((double)angf);
    g_cos[idx] = (float)cos((double)angf);
}

// ---------------- fused RoPE + scale + bf16 hi/lo split, head-major layout -------
__device__ __forceinline__ void splitw(float x, __nv_bfloat16* hi, __nv_bfloat16* lo, size_t i) {
    __nv_bfloat16 h = __float2bfloat16(x);
    hi[i] = h;
    lo[i] = __float2bfloat16(x - __bfloat162float(h));
}

__global__ void convert_kernel()
{
    int idx = blockIdx.x * blockDim.x + threadIdx.x;
    int j  = idx & 63;
    int h  = (idx >> 6) & (H_ - 1);
    int bt = idx >> 10;
    int t  = bt & (T_ - 1);
    int b  = bt >> 11;

    float sn = g_sin[t * HALF_ + j];
    float cs = g_cos[t * HALF_ + j];
    const float scale = 0.088388347648318447f;

    size_t src = (size_t)bt * RS_ + h * D_;
    float q1 = g_qkv[src + j],          q2 = g_qkv[src + j + HALF_];
    float k1 = g_qkv[src + C_ + j],     k2 = g_qkv[src + C_ + j + HALF_];
    float v1 = g_qkv[src + 2*C_ + j],   v2 = g_qkv[src + 2*C_ + j + HALF_];

    float qa = (q1 * cs - q2 * sn) * scale;
    float qb = (q2 * cs + q1 * sn) * scale;
    float ka = k1 * cs - k2 * sn;
    float kb = k2 * cs + k1 * sn;

    size_t dst = ((size_t)(b * H_ + h) * T_ + t) * D_;
    splitw(qa, g_qh, g_ql, dst + j);
    splitw(qb, g_qh, g_ql, dst + j + HALF_);
    splitw(ka, g_kh, g_kl, dst + j);
    splitw(kb, g_kh, g_kl, dst + j + HALF_);
    splitw(v1, g_vh, g_vl, dst + j);
    splitw(v2, g_vh, g_vl, dst + j + HALF_);
}

// =================================================================================
//  Tensor-core causal flash attention:
//  Q fragments hoisted to registers; K/V double-buffered via cp.async.
//  128 q-rows x 64 keys per iter, bf16x3 both GEMMs, epilogue -> bf16 hi/lo.
// =================================================================================
#define FKH 0
#define FKL 16384
#define FVH 32768
#define FVL 49152
#define FSTAGE 65536
#define FSM_TOTAL 131072

__device__ __forceinline__ uint32_t fsw(int r, int c) {   // row, 16B-chunk -> byte offset
    return (uint32_t)(r * 256 + ((((c ^ r) & 7) | (c & 8)) << 4));
}

__global__ void __launch_bounds__(256, 1) flash_mma_kernel()
{
    extern __shared__ char fsm[];
    const uint32_t sb = (uint32_t)__cvta_generic_to_shared(fsm);

    const int i0  = (gridDim.x - 1) - blockIdx.x;   // heavy tiles first
    const int bh  = blockIdx.y;
    const int tid = threadIdx.x;
    const int lane = tid & 31;
    const int w    = tid >> 5;
    const int quad = lane >> 3;
    const int rq   = lane & 7;
    const int lr   = lane >> 2;
    const int lq   = lane & 3;

    const size_t kvbase   = (size_t)bh * (T_ * D_);
    const size_t qrowbase = kvbase + (size_t)i0 * 128 * D_;

    // ---- stage Q tiles (hi at 0, lo at 32768) in buffer-0 region ----
    {
        int r  = tid >> 1;
        int cb = (tid & 1) * 8;
        const size_t g = qrowbase + (size_t)r * D_;
#pragma unroll
        for (int j = 0; j < 8; j++) {
            int c = cb + j;
            uint32_t sw = fsw(r, c);
            *(uint4*)(fsm + sw)         = *(const uint4*)(g_qh + g + c * 8);
            *(uint4*)(fsm + 32768 + sw) = *(const uint4*)(g_ql + g + c * 8);
        }
    }
    __syncthreads();

    // ---- kick off K/V stage 0 into buffer 1 (doesn't overlap Q region) ----
    const int kvr  = tid >> 2;
    const int kvcb = (tid & 3) * 4;
    const int jmax = 2 * i0 + 1;
#define KV_ISSUE(J, BUF) do { \
    const size_t g_ = kvbase + (size_t)((J) * 64 + kvr) * D_; \
    const uint32_t base_ = sb + (BUF) * FSTAGE; \
    _Pragma("unroll") for (int j_ = 0; j_ < 4; j_++) { \
        int c_ = kvcb + j_; \
        uint32_t sw_ = fsw(kvr, c_); \
        CP16(base_ + FKH + sw_, g_kh + g_ + c_ * 8); \
        CP16(base_ + FKL + sw_, g_kl + g_ + c_ * 8); \
        CP16(base_ + FVH + sw_, g_vh + g_ + c_ * 8); \
        CP16(base_ + FVL + sw_, g_vl + g_ + c_ * 8); } \
    CP_COMMIT(); } while (0)

    KV_ISSUE(0, 1);

    // ---- hoist Q fragments into registers (reads buffer-0 region) ----
    const int arow  = 16 * w + (quad & 1) * 8 + rq;
    const int rB    = (quad & 1) * 8 + rq;
    const int cHalf = quad >> 1;

    unsigned qh[8][4], ql[8][4];
#pragma unroll
    for (int kk = 0; kk < 8; kk++) {
        uint32_t aaddr = sb + fsw(arow, 2 * kk + cHalf);
        LDSM_X4(qh[kk][0], qh[kk][1], qh[kk][2], qh[kk][3], aaddr);
        LDSM_X4(ql[kk][0], ql[kk][1], ql[kk][2], ql[kk][3], aaddr + 32768);
    }

    float o[16][4];
#pragma unroll
    for (int dt = 0; dt < 16; dt++)
#pragma unroll
        for (int e = 0; e < 4; e++) o[dt][e] = 0.f;
    float mcur[2] = {-3.4e38f, -3.4e38f};
    float lcur[2] = {0.f, 0.f};

    int buf = 1;
    for (int j0 = 0; j0 <= jmax; j0++) {
        CP_WAIT0();
        __syncthreads();           // KV(j0) landed in `buf`; all warps done with `buf^1`
        if (j0 < jmax) KV_ISSUE(j0 + 1, buf ^ 1);

        const uint32_t kvb = sb + buf * FSTAGE;

        // ---- S = Q K^T ----
        float s[8][4];
#pragma unroll
        for (int nt = 0; nt < 8; nt++)
#pragma unroll
            for (int e = 0; e < 4; e++) s[nt][e] = 0.f;

#pragma unroll
        for (int kk = 0; kk < 8; kk++) {
            const int ca = 2 * kk + cHalf;
            unsigned kh4[4][4], kl4[4][4];
#pragma unroll
            for (int p = 0; p < 4; p++) {
                uint32_t kaddr = kvb + fsw(16 * p + rB, ca);
                LDSM_X4(kh4[p][0], kh4[p][1], kh4[p][2], kh4[p][3], kaddr + FKH);
                LDSM_X4(kl4[p][0], kl4[p][1], kl4[p][2], kl4[p][3], kaddr + FKL);
            }
#pragma unroll
            for (int p = 0; p < 4; p++) {
                unsigned bh0[2] = {kh4[p][0], kh4[p][2]};
                unsigned bh1[2] = {kh4[p][1], kh4[p][3]};
                unsigned bl0[2] = {kl4[p][0], kl4[p][2]};
                unsigned bl1[2] = {kl4[p][1], kl4[p][3]};
                mma16816(s[2*p],   qh[kk], bh0);
                mma16816(s[2*p],   ql[kk], bh0);
                mma16816(s[2*p],   qh[kk], bl0);
                mma16816(s[2*p+1], qh[kk], bh1);
                mma16816(s[2*p+1], ql[kk], bh1);
                mma16816(s[2*p+1], qh[kk], bl1);
            }
        }

        // ---- causal mask (diagonal-straddling tiles only) ----
        if (j0 >= 2 * i0) {
            const int qr0 = i0 * 128 + 16 * w + lr;
            const int kc0 = j0 * 64 + 2 * lq;
#pragma unroll
            for (int nt = 0; nt < 8; nt++)
#pragma unroll
                for (int e = 0; e < 4; e++) {
                    int r = qr0 + (e >> 1) * 8;
                    int c = kc0 + 8 * nt + (e & 1);
                    if (c > r) s[nt][e] = -3.4e38f;
                }
        }

        // ---- online softmax ----
#pragma unroll
        for (int z = 0; z < 2; z++) {
            float mx = -3.4e38f;
#pragma unroll
            for (int nt = 0; nt < 8; nt++)
                mx = fmaxf(mx, fmaxf(s[nt][2*z], s[nt][2*z+1]));
            mx = fmaxf(mx, __shfl_xor_sync(0xffffffffu, mx, 1));
            mx = fmaxf(mx, __shfl_xor_sync(0xffffffffu, mx, 2));
            float mn = fmaxf(mcur[z], mx);
            float alpha = fast_exp(mcur[z] - mn);
            float ls = 0.f;
#pragma unroll
            for (int nt = 0; nt < 8; nt++) {
                float p0 = fast_exp(s[nt][2*z]   - mn);
                float p1 = fast_exp(s[nt][2*z+1] - mn);
                s[nt][2*z] = p0; s[nt][2*z+1] = p1;
                ls += p0 + p1;
            }
            ls += __shfl_xor_sync(0xffffffffu, ls, 1);
            ls += __shfl_xor_sync(0xffffffffu, ls, 2);
            lcur[z] = lcur[z] * alpha + ls;
            mcur[z] = mn;
#pragma unroll
            for (int dt = 0; dt < 16; dt++) {
                o[dt][2*z]   *= alpha;
                o[dt][2*z+1] *= alpha;
            }
        }

        // ---- pack P into A-fragments (hi/lo) from registers ----
        unsigned ph[4][4], pl[4][4];
#pragma unroll
        for (int kk2 = 0; kk2 < 4; kk2++) {
            split2(s[2*kk2][0],   s[2*kk2][1],   ph[kk2][0], pl[kk2][0]);
            split2(s[2*kk2][2],   s[2*kk2][3],   ph[kk2][1], pl[kk2][1]);
            split2(s[2*kk2+1][0], s[2*kk2+1][1], ph[kk2][2], pl[kk2][2]);
            split2(s[2*kk2+1][2], s[2*kk2+1][3], ph[kk2][3], pl[kk2][3]);
        }

        // ---- O += P V ----
#pragma unroll
        for (int kk2 = 0; kk2 < 4; kk2++) {
            const int rV = 16 * kk2 + rB;
#pragma unroll
            for (int p = 0; p < 8; p++) {
                unsigned vh4[4], vl4[4];
                uint32_t vaddr = kvb + fsw(rV, 2 * p + cHalf);
                LDSM_X4_T(vh4[0], vh4[1], vh4[2], vh4[3], vaddr + FVH);
                LDSM_X4_T(vl4[0], vl4[1], vl4[2], vl4[3], vaddr + FVL);
                mma16816(o[2*p],   ph[kk2], &vh4[0]);
                mma16816(o[2*p],   pl[kk2], &vh4[0]);
                mma16816(o[2*p],   ph[kk2], &vl4[0]);
                mma16816(o[2*p+1], ph[kk2], &vh4[2]);
                mma16816(o[2*p+1], pl[kk2], &vh4[2]);
                mma16816(o[2*p+1], ph[kk2], &vl4[2]);
            }
        }
        buf ^= 1;
    }
#undef KV_ISSUE

    // ---- epilogue: O /= l, write bf16 hi/lo splits (flat B,H,T,D) ----
    const float inv0 = 1.f / lcur[0];
    const float inv1 = 1.f / lcur[1];
    const size_t obase = ((size_t)bh * T_ + (size_t)i0 * 128 + 16 * w + lr) * D_;
#pragma unroll
    for (int dt = 0; dt < 16; dt++) {
        int col = 8 * dt + 2 * lq;
        unsigned h0, l0, h1, l1;
        split2(o[dt][0] * inv0, o[dt][1] * inv0, h0, l0);
        split2(o[dt][2] * inv1, o[dt][3] * inv1, h1, l1);
        *(unsigned*)(g_oh + obase + col)          = h0;
        *(unsigned*)(g_ol + obase + col)          = l0;
        *(unsigned*)(g_oh + obase + 8 * D_ + col) = h1;
        *(unsigned*)(g_ol + obase + 8 * D_ + col) = l1;
    }
}

// ---------------- launch ----------------
extern "C" void kernel_launch(void* const* d_in, const int* in_sizes, int n_in,
                              void* d_out, int out_size)
{
    const float* x    = (const float*)d_in[0];
    const float* Wqkv = (const float*)d_in[1];
    const float* Wout = (const float*)d_in[2];
    float* out = (float*)d_out;

    float* qkv = nullptr;
    cudaGetSymbolAddress((void**)&qkv, g_qkv);
    __nv_bfloat16 *xh, *xl, *w1h, *w1l, *w2h, *w2l, *oh, *ol;
    cudaGetSymbolAddress((void**)&xh,  g_xh);
    cudaGetSymbolAddress((void**)&xl,  g_xl);
    cudaGetSymbolAddress((void**)&w1h, g_w1h);
    cudaGetSymbolAddress((void**)&w1l, g_w1l);
    cudaGetSymbolAddress((void**)&w2h, g_w2h);
    cudaGetSymbolAddress((void**)&w2l, g_w2l);
    cudaGetSymbolAddress((void**)&oh,  g_oh);
    cudaGetSymbolAddress((void**)&ol,  g_ol);

    cudaFuncSetAttribute(mma_gemm, cudaFuncAttributeMaxDynamicSharedMemorySize, 131072);
    cudaFuncSetAttribute(flash_mma_kernel, cudaFuncAttributeMaxDynamicSharedMemorySize, FSM_TOTAL);

    // 0) pre-split inputs to bf16 hi/lo (x, Wqkv, Wout)
    split_kernel<<<(M_ * C_ / 4) / 256, 256>>>(x, xh, xl);
    split_kernel<<<((size_t)C_ * N1_ / 4) / 256, 256>>>(Wqkv, w1h, w1l);
    split_kernel<<<((size_t)C_ * C_ / 4) / 256, 256>>>(Wout, w2h, w2l);
    // 1) QKV projection
    mma_gemm<<<dim3(N1_ / 128, M_ / 128), 256, 131072>>>(xh, xl, w1h, w1l, qkv, M_, N1_, C_);
    // 2) RoPE tables + fused rope/scale/split/transpose
    rope_table_kernel<<<(T_ * HALF_ + 255) / 256, 256>>>();
    convert_kernel<<<(B_ * T_ * H_ * HALF_) / 256, 256>>>();
    // 3) tensor-core causal flash attention
    flash_mma_kernel<<<dim3(T_ / 128, BH_), 256, FSM_TOTAL>>>();
    // 4) output projection
    mma_gemm<<<dim3(C_ / 128, M_ / 128), 256, 131072>>>(oh, ol, w2h, w2l, out, M_, C_, C_);
}

// round 6
// speedup vs baseline: 2.9294x; 1.0451x over previous
#include <cuda_runtime.h>
#include <cuda_bf16.h>
#include <cstdint>
#include <math.h>

#define B_   2
#define T_   2048
#define C_   2048
#define H_   16
#define D_   128
#define HALF_ 64
#define M_   (B_*T_)       // 4096
#define N1_  (3*C_)        // 6144
#define RS_  (3*C_)
#define BH_  (B_*H_)       // 32

// ---------------- scratch (device globals) ----------------
__device__ float g_qkv[(size_t)M_ * N1_];              // [B*T, 3*C] fp32 (GEMM1 out)
__device__ float g_sin[T_ * HALF_];
__device__ float g_cos[T_ * HALF_];
__device__ __nv_bfloat16 g_qh[(size_t)BH_ * T_ * D_];  // roped+scaled Q hi/lo, head-major
__device__ __nv_bfloat16 g_ql[(size_t)BH_ * T_ * D_];
__device__ __nv_bfloat16 g_kh[(size_t)BH_ * T_ * D_];
__device__ __nv_bfloat16 g_kl[(size_t)BH_ * T_ * D_];
__device__ __nv_bfloat16 g_vh[(size_t)BH_ * T_ * D_];
__device__ __nv_bfloat16 g_vl[(size_t)BH_ * T_ * D_];
__device__ __nv_bfloat16 g_xh[(size_t)M_ * C_];        // x split [M][K]
__device__ __nv_bfloat16 g_xl[(size_t)M_ * C_];
__device__ __nv_bfloat16 g_w1h[(size_t)C_ * N1_];      // Wqkv split [K][N]
__device__ __nv_bfloat16 g_w1l[(size_t)C_ * N1_];
__device__ __nv_bfloat16 g_w2h[(size_t)C_ * C_];       // Wout split [K][N]
__device__ __nv_bfloat16 g_w2l[(size_t)C_ * C_];
__device__ __nv_bfloat16 g_oh[(size_t)M_ * C_];        // attention out split (flat B,H,T,D)
__device__ __nv_bfloat16 g_ol[(size_t)M_ * C_];

// ---------------- fast exp (FFMA-pipe) --------------
__device__ __forceinline__ float fast_exp(float x) {
    x = fmaxf(x, -87.0f);
    float t = x * 1.4426950408889634f;
    int   i = __float2int_rn(t);
    float f = t - (float)i;
    float p =          1.3333558146428443e-3f;
    p = fmaf(p, f, 9.6181291780723730e-3f);
    p = fmaf(p, f, 5.5504108664821580e-2f);
    p = fmaf(p, f, 2.4022650695910072e-1f);
    p = fmaf(p, f, 6.9314718055994531e-1f);
    p = fmaf(p, f, 1.0f);
    return __int_as_float((i + 127) << 23) * p;
}

// ---------------- MMA / LDSM / cp.async primitives ----------------
#define LDSM_X4(R0,R1,R2,R3,ADDR) \
    asm volatile("ldmatrix.sync.aligned.m8n8.x4.shared.b16 {%0,%1,%2,%3}, [%4];" \
                 : "=r"(R0), "=r"(R1), "=r"(R2), "=r"(R3) : "r"(ADDR))
#define LDSM_X4_T(R0,R1,R2,R3,ADDR) \
    asm volatile("ldmatrix.sync.aligned.m8n8.x4.trans.shared.b16 {%0,%1,%2,%3}, [%4];" \
                 : "=r"(R0), "=r"(R1), "=r"(R2), "=r"(R3) : "r"(ADDR))
#define CP16(DST, SRC) \
    asm volatile("cp.async.cg.shared.global [%0], [%1], 16;" :: "r"(DST), "l"(SRC))
#define CP_COMMIT()  asm volatile("cp.async.commit_group;" ::: "memory")
#define CP_WAIT0()   asm volatile("cp.async.wait_group 0;" ::: "memory")
#define CP_WAIT1()   asm volatile("cp.async.wait_group 1;" ::: "memory")

__device__ __forceinline__ void mma16816(float* d, const unsigned* a, const unsigned* b) {
    asm volatile(
        "mma.sync.aligned.m16n8k16.row.col.f32.bf16.bf16.f32 "
        "{%0,%1,%2,%3}, {%4,%5,%6,%7}, {%8,%9}, {%0,%1,%2,%3};"
        : "+f"(d[0]), "+f"(d[1]), "+f"(d[2]), "+f"(d[3])
        : "r"(a[0]), "r"(a[1]), "r"(a[2]), "r"(a[3]), "r"(b[0]), "r"(b[1]));
}

__device__ __forceinline__ void split2(float x, float y, unsigned& hi, unsigned& lo) {
    __nv_bfloat162 h2 = __floats2bfloat162_rn(x, y);
    float hx = __bfloat162float(h2.x);
    float hy = __bfloat162float(h2.y);
    __nv_bfloat162 l2 = __floats2bfloat162_rn(x - hx, y - hy);
    hi = *reinterpret_cast<unsigned*>(&h2);
    lo = *reinterpret_cast<unsigned*>(&l2);
}

// ---------------- pre-pass: elementwise fp32 -> bf16 hi/lo split (vectorized) ----
__global__ void split_kernel(const float* __restrict__ src,
                             __nv_bfloat16* __restrict__ th,
                             __nv_bfloat16* __restrict__ tl)
{
    size_t i = ((size_t)blockIdx.x * blockDim.x + threadIdx.x) * 4;
    float4 v = *(const float4*)(src + i);
    unsigned h0, l0, h1, l1;
    split2(v.x, v.y, h0, l0);
    split2(v.z, v.w, h1, l1);
    *(uint2*)(th + i) = make_uint2(h0, h1);
    *(uint2*)(tl + i) = make_uint2(l0, l1);
}

// =================================================================================
//  bf16x3 split-precision tensor-core GEMM, cp.async 3-stage pipeline:
//  C[M,N] = (Ah+Al)[M,K] @ (Bh+Bl)[K,N], 128x128x64 stages, 256 thr, mma.m16n8k16
// =================================================================================
#define S_ALO 16384
#define S_BHI 32768
#define S_BLO 49152
#define STAGE_ 65536
#define NSTAGE 3
#define GSM_TOTAL (NSTAGE * STAGE_)

__global__ void __launch_bounds__(256) mma_gemm(const __nv_bfloat16* __restrict__ Ah,
                                                const __nv_bfloat16* __restrict__ Al,
                                                const __nv_bfloat16* __restrict__ Bh,
                                                const __nv_bfloat16* __restrict__ Bl,
                                                float* __restrict__ C,
                                                int M, int N, int K)
{
    extern __shared__ char smem[];
    const uint32_t smem_u32 = (uint32_t)__cvta_generic_to_shared(smem);

    const int tid  = threadIdx.x;
    const int lane = tid & 31;
    const int wid  = tid >> 5;
    const int warp_m = wid & 1;
    const int warp_n = wid >> 1;
    const int quad = lane >> 3;
    const int rq   = lane & 7;

    const int bm = blockIdx.y * 128;
    const int bn = blockIdx.x * 128;

    // staging: A tile 128r x 8 chunks, B tile 64r x 16 chunks, 4 chunks/thread each
    int swA[4], swB[4];
    size_t offA[4], offB[4];
#pragma unroll
    for (int i = 0; i < 4; i++) {
        int ia = i * 256 + tid;
        int ra = ia >> 3, ca = ia & 7;
        swA[i]  = ra * 128 + ((ca ^ (ra & 7)) << 4);
        offA[i] = (size_t)(bm + ra) * K + ca * 8;
        int ib = i * 256 + tid;
        int rb = ib >> 4, cb = ib & 15;
        swB[i]  = rb * 256 + (((cb & 8) | ((cb & 7) ^ (rb & 7))) << 4);
        offB[i] = (size_t)rb * N + bn + cb * 8;
    }

    // ldmatrix lane addressing
    const int aRowL = warp_m * 64 + (quad & 1) * 8 + rq;
    const int kHalf = quad >> 1;
    const int arow7 = aRowL & 7;
    const int arowByte = aRowL * 128;

    const int kL = (quad & 1) * 8 + rq;
    int nbswp[2];
#pragma unroll
    for (int p = 0; p < 2; p++) {
        int nb = warp_n * 4 + (quad >> 1) + p * 2;
        nbswp[p] = (nb & 8) | ((nb & 7) ^ (kL & 7));
    }
    const int bByteBase = kL * 256;

    float acc[4][4][4];
#pragma unroll
    for (int mt = 0; mt < 4; mt++)
#pragma unroll
        for (int nt = 0; nt < 4; nt++)
#pragma unroll
            for (int c = 0; c < 4; c++) acc[mt][nt][c] = 0.f;

#define G_ISSUE(k0, buf) do { \
    const uint32_t b_ = smem_u32 + (buf) * STAGE_; \
    _Pragma("unroll") for (int i = 0; i < 4; i++) { \
        CP16(b_ + swA[i],          Ah + offA[i] + (k0)); \
        CP16(b_ + S_ALO + swA[i],  Al + offA[i] + (k0)); \
        CP16(b_ + S_BHI + swB[i],  Bh + offB[i] + (size_t)(k0) * N); \
        CP16(b_ + S_BLO + swB[i],  Bl + offB[i] + (size_t)(k0) * N); } \
    CP_COMMIT(); } while (0)

    const int KT = K >> 6;
    G_ISSUE(0, 0);
    G_ISSUE(64, 1);

    for (int kt = 0; kt < KT; kt++) {
        if (kt + 1 < KT) { CP_WAIT1(); } else { CP_WAIT0(); }
        __syncthreads();
        if (kt + 2 < KT) G_ISSUE((kt + 2) * 64, (kt + 2) % NSTAGE);

        const uint32_t sbase = smem_u32 + (kt % NSTAGE) * STAGE_;
#pragma unroll
        for (int kk = 0; kk < 4; kk++) {
            unsigned ah[4][4], al[4][4], bh[2][4], bl[2][4];
            const int asw = ((2 * kk + kHalf) ^ arow7) * 16;
#pragma unroll
            for (int mt = 0; mt < 4; mt++) {
                uint32_t ad = sbase + arowByte + mt * 2048 + asw;
                LDSM_X4(ah[mt][0], ah[mt][1], ah[mt][2], ah[mt][3], ad);
                LDSM_X4(al[mt][0], al[mt][1], al[mt][2], al[mt][3], ad + S_ALO);
            }
#pragma unroll
            for (int p = 0; p < 2; p++) {
                uint32_t bd = sbase + kk * 4096 + bByteBase + nbswp[p] * 16;
                LDSM_X4_T(bh[p][0], bh[p][1], bh[p][2], bh[p][3], bd + S_BHI);
                LDSM_X4_T(bl[p][0], bl[p][1], bl[p][2], bl[p][3], bd + S_BLO);
            }
#pragma unroll
            for (int mt = 0; mt < 4; mt++)
#pragma unroll
                for (int nt = 0; nt < 4; nt++) {
                    const unsigned* bph = &bh[nt >> 1][(nt & 1) * 2];
                    const unsigned* bpl = &bl[nt >> 1][(nt & 1) * 2];
                    mma16816(acc[mt][nt], ah[mt], bph);
                    mma16816(acc[mt][nt], al[mt], bph);
                    mma16816(acc[mt][nt], ah[mt], bpl);
                }
        }
        __syncthreads();
    }
#undef G_ISSUE

    const int r0 = bm + warp_m * 64 + (lane >> 2);
    const int c0 = bn + warp_n * 32 + (lane & 3) * 2;
#pragma unroll
    for (int mt = 0; mt < 4; mt++)
#pragma unroll
        for (int nt = 0; nt < 4; nt++) {
            float* p0 = C + (size_t)(r0 + mt * 16) * N + c0 + nt * 8;
            float* p1 = C + (size_t)(r0 + mt * 16 + 8) * N + c0 + nt * 8;
            *(float2*)p0 = make_float2(acc[mt][nt][0], acc[mt][nt][1]);
            *(float2*)p1 = make_float2(acc[mt][nt][2], acc[mt][nt][3]);
        }
}

// ---------------- RoPE tables (fp64 angles) ------
__global__ void rope_table_kernel()
{
    int idx = blockIdx.x * blockDim.x + threadIdx.x;
    if (idx >= T_ * HALF_) return;
    int t = idx / HALF_, j = idx % HALF_;
    double div  = exp(-(double)(2 * j) * 9.210340371976184 / 128.0);
    float  divf = (float)div;
    float  angf = (float)t * divf;
    g_sin[idx] = (float)sin((double)angf);
    g_cos[idx] = (float)cos((double)angf);
}

// ---------------- fused RoPE + scale + bf16 hi/lo split, head-major layout -------
__device__ __forceinline__ void splitw(float x, __nv_bfloat16* hi, __nv_bfloat16* lo, size_t i) {
    __nv_bfloat16 h = __float2bfloat16(x);
    hi[i] = h;
    lo[i] = __float2bfloat16(x - __bfloat162float(h));
}

__global__ void convert_kernel()
{
    int idx = blockIdx.x * blockDim.x + threadIdx.x;
    int j  = idx & 63;
    int h  = (idx >> 6) & (H_ - 1);
    int bt = idx >> 10;
    int t  = bt & (T_ - 1);
    int b  = bt >> 11;

    float sn = g_sin[t * HALF_ + j];
    float cs = g_cos[t * HALF_ + j];
    const float scale = 0.088388347648318447f;

    size_t src = (size_t)bt * RS_ + h * D_;
    float q1 = g_qkv[src + j],          q2 = g_qkv[src + j + HALF_];
    float k1 = g_qkv[src + C_ + j],     k2 = g_qkv[src + C_ + j + HALF_];
    float v1 = g_qkv[src + 2*C_ + j],   v2 = g_qkv[src + 2*C_ + j + HALF_];

    float qa = (q1 * cs - q2 * sn) * scale;
    float qb = (q2 * cs + q1 * sn) * scale;
    float ka = k1 * cs - k2 * sn;
    float kb = k2 * cs + k1 * sn;

    size_t dst = ((size_t)(b * H_ + h) * T_ + t) * D_;
    splitw(qa, g_qh, g_ql, dst + j);
    splitw(qb, g_qh, g_ql, dst + j + HALF_);
    splitw(ka, g_kh, g_kl, dst + j);
    splitw(kb, g_kh, g_kl, dst + j + HALF_);
    splitw(v1, g_vh, g_vl, dst + j);
    splitw(v2, g_vh, g_vl, dst + j + HALF_);
}

// =================================================================================
//  Tensor-core causal flash attention:
//  Q fragments hoisted to registers; K/V double-buffered via cp.async.
// =================================================================================
#define FKH 0
#define FKL 16384
#define FVH 32768
#define FVL 49152
#define FSTAGE 65536
#define FSM_TOTAL 131072

__device__ __forceinline__ uint32_t fsw(int r, int c) {
    return (uint32_t)(r * 256 + ((((c ^ r) & 7) | (c & 8)) << 4));
}

__global__ void __launch_bounds__(256, 1) flash_mma_kernel()
{
    extern __shared__ char fsm[];
    const uint32_t sb = (uint32_t)__cvta_generic_to_shared(fsm);

    const int i0  = (gridDim.x - 1) - blockIdx.x;
    const int bh  = blockIdx.y;
    const int tid = threadIdx.x;
    const int lane = tid & 31;
    const int w    = tid >> 5;
    const int quad = lane >> 3;
    const int rq   = lane & 7;
    const int lr   = lane >> 2;
    const int lq   = lane & 3;

    const size_t kvbase   = (size_t)bh * (T_ * D_);
    const size_t qrowbase = kvbase + (size_t)i0 * 128 * D_;

    {
        int r  = tid >> 1;
        int cb = (tid & 1) * 8;
        const size_t g = qrowbase + (size_t)r * D_;
#pragma unroll
        for (int j = 0; j < 8; j++) {
            int c = cb + j;
            uint32_t sw = fsw(r, c);
            *(uint4*)(fsm + sw)         = *(const uint4*)(g_qh + g + c * 8);
            *(uint4*)(fsm + 32768 + sw) = *(const uint4*)(g_ql + g + c * 8);
        }
    }
    __syncthreads();

    const int kvr  = tid >> 2;
    const int kvcb = (tid & 3) * 4;
    const int jmax = 2 * i0 + 1;
#define KV_ISSUE(J, BUF) do { \
    const size_t g_ = kvbase + (size_t)((J) * 64 + kvr) * D_; \
    const uint32_t base_ = sb + (BUF) * FSTAGE; \
    _Pragma("unroll") for (int j_ = 0; j_ < 4; j_++) { \
        int c_ = kvcb + j_; \
        uint32_t sw_ = fsw(kvr, c_); \
        CP16(base_ + FKH + sw_, g_kh + g_ + c_ * 8); \
        CP16(base_ + FKL + sw_, g_kl + g_ + c_ * 8); \
        CP16(base_ + FVH + sw_, g_vh + g_ + c_ * 8); \
        CP16(base_ + FVL + sw_, g_vl + g_ + c_ * 8); } \
    CP_COMMIT(); } while (0)

    KV_ISSUE(0, 1);

    const int arow  = 16 * w + (quad & 1) * 8 + rq;
    const int rB    = (quad & 1) * 8 + rq;
    const int cHalf = quad >> 1;

    unsigned qh[8][4], ql[8][4];
#pragma unroll
    for (int kk = 0; kk < 8; kk++) {
        uint32_t aaddr = sb + fsw(arow, 2 * kk + cHalf);
        LDSM_X4(qh[kk][0], qh[kk][1], qh[kk][2], qh[kk][3], aaddr);
        LDSM_X4(ql[kk][0], ql[kk][1], ql[kk][2], ql[kk][3], aaddr + 32768);
    }

    float o[16][4];
#pragma unroll
    for (int dt = 0; dt < 16; dt++)
#pragma unroll
        for (int e = 0; e < 4; e++) o[dt][e] = 0.f;
    float mcur[2] = {-3.4e38f, -3.4e38f};
    float lcur[2] = {0.f, 0.f};

    int buf = 1;
    for (int j0 = 0; j0 <= jmax; j0++) {
        CP_WAIT0();
        __syncthreads();
        if (j0 < jmax) KV_ISSUE(j0 + 1, buf ^ 1);

        const uint32_t kvb = sb + buf * FSTAGE;

        float s[8][4];
#pragma unroll
        for (int nt = 0; nt < 8; nt++)
#pragma unroll
            for (int e = 0; e < 4; e++) s[nt][e] = 0.f;

#pragma unroll
        for (int kk = 0; kk < 8; kk++) {
            const int ca = 2 * kk + cHalf;
            unsigned kh4[4][4], kl4[4][4];
#pragma unroll
            for (int p = 0; p < 4; p++) {
                uint32_t kaddr = kvb + fsw(16 * p + rB, ca);
                LDSM_X4(kh4[p][0], kh4[p][1], kh4[p][2], kh4[p][3], kaddr + FKH);
                LDSM_X4(kl4[p][0], kl4[p][1], kl4[p][2], kl4[p][3], kaddr + FKL);
            }
#pragma unroll
            for (int p = 0; p < 4; p++) {
                unsigned bh0[2] = {kh4[p][0], kh4[p][2]};
                unsigned bh1[2] = {kh4[p][1], kh4[p][3]};
                unsigned bl0[2] = {kl4[p][0], kl4[p][2]};
                unsigned bl1[2] = {kl4[p][1], kl4[p][3]};
                mma16816(s[2*p],   qh[kk], bh0);
                mma16816(s[2*p],   ql[kk], bh0);
                mma16816(s[2*p],   qh[kk], bl0);
                mma16816(s[2*p+1], qh[kk], bh1);
                mma16816(s[2*p+1], ql[kk], bh1);
                mma16816(s[2*p+1], qh[kk], bl1);
            }
        }

        if (j0 >= 2 * i0) {
            const int qr0 = i0 * 128 + 16 * w + lr;
            const int kc0 = j0 * 64 + 2 * lq;
#pragma unroll
            for (int nt = 0; nt < 8; nt++)
#pragma unroll
                for (int e = 0; e < 4; e++) {
                    int r = qr0 + (e >> 1) * 8;
                    int c = kc0 + 8 * nt + (e & 1);
                    if (c > r) s[nt][e] = -3.4e38f;
                }
        }

#pragma unroll
        for (int z = 0; z < 2; z++) {
            float mx = -3.4e38f;
#pragma unroll
            for (int nt = 0; nt < 8; nt++)
                mx = fmaxf(mx, fmaxf(s[nt][2*z], s[nt][2*z+1]));
            mx = fmaxf(mx, __shfl_xor_sync(0xffffffffu, mx, 1));
            mx = fmaxf(mx, __shfl_xor_sync(0xffffffffu, mx, 2));
            float mn = fmaxf(mcur[z], mx);
            float alpha = fast_exp(mcur[z] - mn);
            float ls = 0.f;
#pragma unroll
            for (int nt = 0; nt < 8; nt++) {
                float p0 = fast_exp(s[nt][2*z]   - mn);
                float p1 = fast_exp(s[nt][2*z+1] - mn);
                s[nt][2*z] = p0; s[nt][2*z+1] = p1;
                ls += p0 + p1;
            }
            ls += __shfl_xor_sync(0xffffffffu, ls, 1);
            ls += __shfl_xor_sync(0xffffffffu, ls, 2);
            lcur[z] = lcur[z] * alpha + ls;
            mcur[z] = mn;
#pragma unroll
            for (int dt = 0; dt < 16; dt++) {
                o[dt][2*z]   *= alpha;
                o[dt][2*z+1] *= alpha;
            }
        }

        unsigned ph[4][4], pl[4][4];
#pragma unroll
        for (int kk2 = 0; kk2 < 4; kk2++) {
            split2(s[2*kk2][0],   s[2*kk2][1],   ph[kk2][0], pl[kk2][0]);
            split2(s[2*kk2][2],   s[2*kk2][3],   ph[kk2][1], pl[kk2][1]);
            split2(s[2*kk2+1][0], s[2*kk2+1][1], ph[kk2][2], pl[kk2][2]);
            split2(s[2*kk2+1][2], s[2*kk2+1][3], ph[kk2][3], pl[kk2][3]);
        }

#pragma unroll
        for (int kk2 = 0; kk2 < 4; kk2++) {
            const int rV = 16 * kk2 + rB;
#pragma unroll
            for (int p = 0; p < 8; p++) {
                unsigned vh4[4], vl4[4];
                uint32_t vaddr = kvb + fsw(rV, 2 * p + cHalf);
                LDSM_X4_T(vh4[0], vh4[1], vh4[2], vh4[3], vaddr + FVH);
                LDSM_X4_T(vl4[0], vl4[1], vl4[2], vl4[3], vaddr + FVL);
                mma16816(o[2*p],   ph[kk2], &vh4[0]);
                mma16816(o[2*p],   pl[kk2], &vh4[0]);
                mma16816(o[2*p],   ph[kk2], &vl4[0]);
                mma16816(o[2*p+1], ph[kk2], &vh4[2]);
                mma16816(o[2*p+1], pl[kk2], &vh4[2]);
                mma16816(o[2*p+1], ph[kk2], &vl4[2]);
            }
        }
        buf ^= 1;
    }
#undef KV_ISSUE

    const float inv0 = 1.f / lcur[0];
    const float inv1 = 1.f / lcur[1];
    const size_t obase = ((size_t)bh * T_ + (size_t)i0 * 128 + 16 * w + lr) * D_;
#pragma unroll
    for (int dt = 0; dt < 16; dt++) {
        int col = 8 * dt + 2 * lq;
        unsigned h0, l0, h1, l1;
        split2(o[dt][0] * inv0, o[dt][1] * inv0, h0, l0);
        split2(o[dt][2] * inv1, o[dt][3] * inv1, h1, l1);
        *(unsigned*)(g_oh + obase + col)          = h0;
        *(unsigned*)(g_ol + obase + col)          = l0;
        *(unsigned*)(g_oh + obase + 8 * D_ + col) = h1;
        *(unsigned*)(g_ol + obase + 8 * D_ + col) = l1;
    }
}

// ---------------- launch ----------------
extern "C" void kernel_launch(void* const* d_in, const int* in_sizes, int n_in,
                              void* d_out, int out_size)
{
    const float* x    = (const float*)d_in[0];
    const float* Wqkv = (const float*)d_in[1];
    const float* Wout = (const float*)d_in[2];
    float* out = (float*)d_out;

    float* qkv = nullptr;
    cudaGetSymbolAddress((void**)&qkv, g_qkv);
    __nv_bfloat16 *xh, *xl, *w1h, *w1l, *w2h, *w2l, *oh, *ol;
    cudaGetSymbolAddress((void**)&xh,  g_xh);
    cudaGetSymbolAddress((void**)&xl,  g_xl);
    cudaGetSymbolAddress((void**)&w1h, g_w1h);
    cudaGetSymbolAddress((void**)&w1l, g_w1l);
    cudaGetSymbolAddress((void**)&w2h, g_w2h);
    cudaGetSymbolAddress((void**)&w2l, g_w2l);
    cudaGetSymbolAddress((void**)&oh,  g_oh);
    cudaGetSymbolAddress((void**)&ol,  g_ol);

    cudaFuncSetAttribute(mma_gemm, cudaFuncAttributeMaxDynamicSharedMemorySize, GSM_TOTAL);
    cudaFuncSetAttribute(flash_mma_kernel, cudaFuncAttributeMaxDynamicSharedMemorySize, FSM_TOTAL);

    // 0) pre-split inputs to bf16 hi/lo (x, Wqkv, Wout)
    split_kernel<<<(M_ * C_ / 4) / 256, 256>>>(x, xh, xl);
    split_kernel<<<((size_t)C_ * N1_ / 4) / 256, 256>>>(Wqkv, w1h, w1l);
    split_kernel<<<((size_t)C_ * C_ / 4) / 256, 256>>>(Wout, w2h, w2l);
    // 1) QKV projection
    mma_gemm<<<dim3(N1_ / 128, M_ / 128), 256, GSM_TOTAL>>>(xh, xl, w1h, w1l, qkv, M_, N1_, C_);
    // 2) RoPE tables + fused rope/scale/split/transpose
    rope_table_kernel<<<(T_ * HALF_ + 255) / 256, 256>>>();
    convert_kernel<<<(B_ * T_ * H_ * HALF_) / 256, 256>>>();
    // 3) tensor-core causal flash attention
    flash_mma_kernel<<<dim3(T_ / 128, BH_), 256, FSM_TOTAL>>>();
    // 4) output projection
    mma_gemm<<<dim3(C_ / 128, M_ / 128), 256, GSM_TOTAL>>>(oh, ol, w2h, w2l, out, M_, C_, C_);
}

// round 7
// speedup vs baseline: 3.0405x; 1.0379x over previous
#include <cuda_runtime.h>
#include <cuda_bf16.h>
#include <cstdint>
#include <math.h>

#define B_   2
#define T_   2048
#define C_   2048
#define H_   16
#define D_   128
#define HALF_ 64
#define M_   (B_*T_)       // 4096
#define N1_  (3*C_)        // 6144
#define RS_  (3*C_)
#define BH_  (B_*H_)       // 32

// ---------------- scratch (device globals) ----------------
__device__ float g_qkv[(size_t)M_ * N1_];              // [B*T, 3*C] fp32 (GEMM1 out)
__device__ float g_sin[T_ * HALF_];
__device__ float g_cos[T_ * HALF_];
__device__ __nv_bfloat16 g_qh[(size_t)BH_ * T_ * D_];  // roped+scaled Q hi/lo, head-major
__device__ __nv_bfloat16 g_ql[(size_t)BH_ * T_ * D_];
__device__ __nv_bfloat16 g_kh[(size_t)BH_ * T_ * D_];
__device__ __nv_bfloat16 g_kl[(size_t)BH_ * T_ * D_];
__device__ __nv_bfloat16 g_vh[(size_t)BH_ * T_ * D_];
__device__ __nv_bfloat16 g_vl[(size_t)BH_ * T_ * D_];
__device__ __nv_bfloat16 g_xh[(size_t)M_ * C_];        // x split [M][K]
__device__ __nv_bfloat16 g_xl[(size_t)M_ * C_];
__device__ __nv_bfloat16 g_w1h[(size_t)C_ * N1_];      // Wqkv split [K][N]
__device__ __nv_bfloat16 g_w1l[(size_t)C_ * N1_];
__device__ __nv_bfloat16 g_w2h[(size_t)C_ * C_];       // Wout split [K][N]
__device__ __nv_bfloat16 g_w2l[(size_t)C_ * C_];
__device__ __nv_bfloat16 g_oh[(size_t)M_ * C_];        // attention out split (flat B,H,T,D)
__device__ __nv_bfloat16 g_ol[(size_t)M_ * C_];

// ---------------- fast exp (FFMA-pipe) --------------
__device__ __forceinline__ float fast_exp(float x) {
    x = fmaxf(x, -87.0f);
    float t = x * 1.4426950408889634f;
    int   i = __float2int_rn(t);
    float f = t - (float)i;
    float p =          1.3333558146428443e-3f;
    p = fmaf(p, f, 9.6181291780723730e-3f);
    p = fmaf(p, f, 5.5504108664821580e-2f);
    p = fmaf(p, f, 2.4022650695910072e-1f);
    p = fmaf(p, f, 6.9314718055994531e-1f);
    p = fmaf(p, f, 1.0f);
    return __int_as_float((i + 127) << 23) * p;
}

// ---------------- MMA / LDSM / cp.async primitives ----------------
#define LDSM_X4(R0,R1,R2,R3,ADDR) \
    asm volatile("ldmatrix.sync.aligned.m8n8.x4.shared.b16 {%0,%1,%2,%3}, [%4];" \
                 : "=r"(R0), "=r"(R1), "=r"(R2), "=r"(R3) : "r"(ADDR))
#define LDSM_X4_T(R0,R1,R2,R3,ADDR) \
    asm volatile("ldmatrix.sync.aligned.m8n8.x4.trans.shared.b16 {%0,%1,%2,%3}, [%4];" \
                 : "=r"(R0), "=r"(R1), "=r"(R2), "=r"(R3) : "r"(ADDR))
#define CP16(DST, SRC) \
    asm volatile("cp.async.cg.shared.global [%0], [%1], 16;" :: "r"(DST), "l"(SRC))
#define CP_COMMIT()  asm volatile("cp.async.commit_group;" ::: "memory")
#define CP_WAIT0()   asm volatile("cp.async.wait_group 0;" ::: "memory")
#define CP_WAIT1()   asm volatile("cp.async.wait_group 1;" ::: "memory")

__device__ __forceinline__ void mma16816(float* d, const unsigned* a, const unsigned* b) {
    asm volatile(
        "mma.sync.aligned.m16n8k16.row.col.f32.bf16.bf16.f32 "
        "{%0,%1,%2,%3}, {%4,%5,%6,%7}, {%8,%9}, {%0,%1,%2,%3};"
        : "+f"(d[0]), "+f"(d[1]), "+f"(d[2]), "+f"(d[3])
        : "r"(a[0]), "r"(a[1]), "r"(a[2]), "r"(a[3]), "r"(b[0]), "r"(b[1]));
}

__device__ __forceinline__ void split2(float x, float y, unsigned& hi, unsigned& lo) {
    __nv_bfloat162 h2 = __floats2bfloat162_rn(x, y);
    float hx = __bfloat162float(h2.x);
    float hy = __bfloat162float(h2.y);
    __nv_bfloat162 l2 = __floats2bfloat162_rn(x - hx, y - hy);
    hi = *reinterpret_cast<unsigned*>(&h2);
    lo = *reinterpret_cast<unsigned*>(&l2);
}

// ---------------- pre-pass: elementwise fp32 -> bf16 hi/lo split (vectorized) ----
__global__ void split_kernel(const float* __restrict__ src,
                             __nv_bfloat16* __restrict__ th,
                             __nv_bfloat16* __restrict__ tl)
{
    size_t i = ((size_t)blockIdx.x * blockDim.x + threadIdx.x) * 4;
    float4 v = *(const float4*)(src + i);
    unsigned h0, l0, h1, l1;
    split2(v.x, v.y, h0, l0);
    split2(v.z, v.w, h1, l1);
    *(uint2*)(th + i) = make_uint2(h0, h1);
    *(uint2*)(tl + i) = make_uint2(l0, l1);
}

// =================================================================================
//  bf16x3 split-precision tensor-core GEMM, cp.async 3-stage pipeline, BK=32,
//  2 CTAs/SM. A stage: 128 rows x 128B (chunks 0-3 = hi, 4-7 = lo, XOR-8 swizzle).
//  B stage: hi 32x256B + lo 32x256B.
// =================================================================================
#define SGBH  16384
#define SGBL  24576
#define STAGE_ 32768
#define NSTAGE 3
#define GSM_TOTAL (NSTAGE * STAGE_)   // 98304

__global__ void __launch_bounds__(256, 2) mma_gemm(const __nv_bfloat16* __restrict__ Ah,
                                                   const __nv_bfloat16* __restrict__ Al,
                                                   const __nv_bfloat16* __restrict__ Bh,
                                                   const __nv_bfloat16* __restrict__ Bl,
                                                   float* __restrict__ C,
                                                   int M, int N, int K)
{
    extern __shared__ char smem[];
    const uint32_t smem_u32 = (uint32_t)__cvta_generic_to_shared(smem);

    const int tid  = threadIdx.x;
    const int lane = tid & 31;
    const int wid  = tid >> 5;
    const int warp_m = wid & 1;
    const int warp_n = wid >> 1;
    const int quad = lane >> 3;
    const int rq   = lane & 7;

    const int bm = blockIdx.y * 128;
    const int bn = blockIdx.x * 128;

    // ---- staging: A 128r x 8 logical chunks (0-3 hi, 4-7 lo); B 2 x 32r x 16 chunks
    uint32_t swA[4], swB[4];
    const __nv_bfloat16* pA[4];
    const __nv_bfloat16* pB[4];
#pragma unroll
    for (int i = 0; i < 4; i++) {
        int ia = i * 256 + tid;
        int ra = ia >> 3, ca = ia & 7;
        swA[i] = ra * 128 + ((ca ^ (ra & 7)) << 4);
        pA[i]  = (ca < 4 ? Ah : Al) + (size_t)(bm + ra) * K + (ca & 3) * 8;
        int hilo = ia >> 9;
        int rem  = ia & 511;
        int rb = rem >> 4, cb = rem & 15;
        swB[i] = (hilo ? SGBL : SGBH) + rb * 256 + (((cb & 8) | ((cb & 7) ^ (rb & 7))) << 4);
        pB[i]  = (hilo ? Bl : Bh) + (size_t)rb * N + bn + cb * 8;
    }

    // ---- ldmatrix lane addressing ----
    const int aRowL = warp_m * 64 + (quad & 1) * 8 + rq;
    const int kHalf = quad >> 1;
    const int arow7 = aRowL & 7;
    const int arowByte = aRowL * 128;

    const int kL = (quad & 1) * 8 + rq;
    int nbswp[2];
#pragma unroll
    for (int p = 0; p < 2; p++) {
        int nb = warp_n * 4 + (quad >> 1) + p * 2;
        nbswp[p] = (nb & 8) | ((nb & 7) ^ (kL & 7));
    }
    const int bByteBase = kL * 256;

    float acc[4][4][4];
#pragma unroll
    for (int mt = 0; mt < 4; mt++)
#pragma unroll
        for (int nt = 0; nt < 4; nt++)
#pragma unroll
            for (int c = 0; c < 4; c++) acc[mt][nt][c] = 0.f;

#define G_ISSUE(k0, buf) do { \
    const uint32_t b_ = smem_u32 + (buf) * STAGE_; \
    _Pragma("unroll") for (int i = 0; i < 4; i++) { \
        CP16(b_ + swA[i], pA[i] + (k0)); \
        CP16(b_ + swB[i], pB[i] + (size_t)(k0) * N); } \
    CP_COMMIT(); } while (0)

    const int KT = K >> 5;    // 64 stages of 32
    G_ISSUE(0, 0);
    G_ISSUE(32, 1);

    for (int kt = 0; kt < KT; kt++) {
        if (kt + 1 < KT) { CP_WAIT1(); } else { CP_WAIT0(); }
        __syncthreads();
        if (kt + 2 < KT) G_ISSUE((kt + 2) * 32, (kt + 2) % NSTAGE);

        const uint32_t sbase = smem_u32 + (kt % NSTAGE) * STAGE_;
#pragma unroll
        for (int kk = 0; kk < 2; kk++) {
            unsigned ah[4][4], al[4][4], bh[2][4], bl[2][4];
            const int chi = 2 * kk + kHalf;
            const int asw_h = ((chi)     ^ arow7) << 4;
            const int asw_l = ((chi + 4) ^ arow7) << 4;
#pragma unroll
            for (int mt = 0; mt < 4; mt++) {
                uint32_t ad = sbase + arowByte + mt * 2048;
                LDSM_X4(ah[mt][0], ah[mt][1], ah[mt][2], ah[mt][3], ad + asw_h);
                LDSM_X4(al[mt][0], al[mt][1], al[mt][2], al[mt][3], ad + asw_l);
            }
#pragma unroll
            for (int p = 0; p < 2; p++) {
                uint32_t bd = sbase + kk * 4096 + bByteBase + nbswp[p] * 16;
                LDSM_X4_T(bh[p][0], bh[p][1], bh[p][2], bh[p][3], bd + SGBH);
                LDSM_X4_T(bl[p][0], bl[p][1], bl[p][2], bl[p][3], bd + SGBL);
            }
#pragma unroll
            for (int mt = 0; mt < 4; mt++)
#pragma unroll
                for (int nt = 0; nt < 4; nt++) {
                    const unsigned* bph = &bh[nt >> 1][(nt & 1) * 2];
                    const unsigned* bpl = &bl[nt >> 1][(nt & 1) * 2];
                    mma16816(acc[mt][nt], ah[mt], bph);
                    mma16816(acc[mt][nt], al[mt], bph);
                    mma16816(acc[mt][nt], ah[mt], bpl);
                }
        }
    }
#undef G_ISSUE

    __syncthreads();
    const int r0 = bm + warp_m * 64 + (lane >> 2);
    const int c0 = bn + warp_n * 32 + (lane & 3) * 2;
#pragma unroll
    for (int mt = 0; mt < 4; mt++)
#pragma unroll
        for (int nt = 0; nt < 4; nt++) {
            float* p0 = C + (size_t)(r0 + mt * 16) * N + c0 + nt * 8;
            float* p1 = C + (size_t)(r0 + mt * 16 + 8) * N + c0 + nt * 8;
            *(float2*)p0 = make_float2(acc[mt][nt][0], acc[mt][nt][1]);
            *(float2*)p1 = make_float2(acc[mt][nt][2], acc[mt][nt][3]);
        }
}

// ---------------- RoPE tables (fp64 angles) ------
__global__ void rope_table_kernel()
{
    int idx = blockIdx.x * blockDim.x + threadIdx.x;
    if (idx >= T_ * HALF_) return;
    int t = idx / HALF_, j = idx % HALF_;
    double div  = exp(-(double)(2 * j) * 9.210340371976184 / 128.0);
    float  divf = (float)div;
    float  angf = (float)t * divf;
    g_sin[idx] = (float)sin((double)angf);
    g_cos[idx] = (float)cos((double)angf);
}

// ---------------- fused RoPE + scale + bf16 hi/lo split, head-major layout -------
__device__ __forceinline__ void splitw(float x, __nv_bfloat16* hi, __nv_bfloat16* lo, size_t i) {
    __nv_bfloat16 h = __float2bfloat16(x);
    hi[i] = h;
    lo[i] = __float2bfloat16(x - __bfloat162float(h));
}

__global__ void convert_kernel()
{
    int idx = blockIdx.x * blockDim.x + threadIdx.x;
    int j  = idx & 63;
    int h  = (idx >> 6) & (H_ - 1);
    int bt = idx >> 10;
    int t  = bt & (T_ - 1);
    int b  = bt >> 11;

    float sn = g_sin[t * HALF_ + j];
    float cs = g_cos[t * HALF_ + j];
    const float scale = 0.088388347648318447f;

    size_t src = (size_t)bt * RS_ + h * D_;
    float q1 = g_qkv[src + j],          q2 = g_qkv[src + j + HALF_];
    float k1 = g_qkv[src + C_ + j],     k2 = g_qkv[src + C_ + j + HALF_];
    float v1 = g_qkv[src + 2*C_ + j],   v2 = g_qkv[src + 2*C_ + j + HALF_];

    float qa = (q1 * cs - q2 * sn) * scale;
    float qb = (q2 * cs + q1 * sn) * scale;
    float ka = k1 * cs - k2 * sn;
    float kb = k2 * cs + k1 * sn;

    size_t dst = ((size_t)(b * H_ + h) * T_ + t) * D_;
    splitw(qa, g_qh, g_ql, dst + j);
    splitw(qb, g_qh, g_ql, dst + j + HALF_);
    splitw(ka, g_kh, g_kl, dst + j);
    splitw(kb, g_kh, g_kl, dst + j + HALF_);
    splitw(v1, g_vh, g_vl, dst + j);
    splitw(v2, g_vh, g_vl, dst + j + HALF_);
}

// =================================================================================
//  Tensor-core causal flash attention (unchanged from round 6)
// =================================================================================
#define FKH 0
#define FKL 16384
#define FVH 32768
#define FVL 49152
#define FSTAGE 65536
#define FSM_TOTAL 131072

__device__ __forceinline__ uint32_t fsw(int r, int c) {
    return (uint32_t)(r * 256 + ((((c ^ r) & 7) | (c & 8)) << 4));
}

__global__ void __launch_bounds__(256, 1) flash_mma_kernel()
{
    extern __shared__ char fsm[];
    const uint32_t sb = (uint32_t)__cvta_generic_to_shared(fsm);

    const int i0  = (gridDim.x - 1) - blockIdx.x;
    const int bh  = blockIdx.y;
    const int tid = threadIdx.x;
    const int lane = tid & 31;
    const int w    = tid >> 5;
    const int quad = lane >> 3;
    const int rq   = lane & 7;
    const int lr   = lane >> 2;
    const int lq   = lane & 3;

    const size_t kvbase   = (size_t)bh * (T_ * D_);
    const size_t qrowbase = kvbase + (size_t)i0 * 128 * D_;

    {
        int r  = tid >> 1;
        int cb = (tid & 1) * 8;
        const size_t g = qrowbase + (size_t)r * D_;
#pragma unroll
        for (int j = 0; j < 8; j++) {
            int c = cb + j;
            uint32_t sw = fsw(r, c);
            *(uint4*)(fsm + sw)         = *(const uint4*)(g_qh + g + c * 8);
            *(uint4*)(fsm + 32768 + sw) = *(const uint4*)(g_ql + g + c * 8);
        }
    }
    __syncthreads();

    const int kvr  = tid >> 2;
    const int kvcb = (tid & 3) * 4;
    const int jmax = 2 * i0 + 1;
#define KV_ISSUE(J, BUF) do { \
    const size_t g_ = kvbase + (size_t)((J) * 64 + kvr) * D_; \
    const uint32_t base_ = sb + (BUF) * FSTAGE; \
    _Pragma("unroll") for (int j_ = 0; j_ < 4; j_++) { \
        int c_ = kvcb + j_; \
        uint32_t sw_ = fsw(kvr, c_); \
        CP16(base_ + FKH + sw_, g_kh + g_ + c_ * 8); \
        CP16(base_ + FKL + sw_, g_kl + g_ + c_ * 8); \
        CP16(base_ + FVH + sw_, g_vh + g_ + c_ * 8); \
        CP16(base_ + FVL + sw_, g_vl + g_ + c_ * 8); } \
    CP_COMMIT(); } while (0)

    KV_ISSUE(0, 1);

    const int arow  = 16 * w + (quad & 1) * 8 + rq;
    const int rB    = (quad & 1) * 8 + rq;
    const int cHalf = quad >> 1;

    unsigned qh[8][4], ql[8][4];
#pragma unroll
    for (int kk = 0; kk < 8; kk++) {
        uint32_t aaddr = sb + fsw(arow, 2 * kk + cHalf);
        LDSM_X4(qh[kk][0], qh[kk][1], qh[kk][2], qh[kk][3], aaddr);
        LDSM_X4(ql[kk][0], ql[kk][1], ql[kk][2], ql[kk][3], aaddr + 32768);
    }

    float o[16][4];
#pragma unroll
    for (int dt = 0; dt < 16; dt++)
#pragma unroll
        for (int e = 0; e < 4; e++) o[dt][e] = 0.f;
    float mcur[2] = {-3.4e38f, -3.4e38f};
    float lcur[2] = {0.f, 0.f};

    int buf = 1;
    for (int j0 = 0; j0 <= jmax; j0++) {
        CP_WAIT0();
        __syncthreads();
        if (j0 < jmax) KV_ISSUE(j0 + 1, buf ^ 1);

        const uint32_t kvb = sb + buf * FSTAGE;

        float s[8][4];
#pragma unroll
        for (int nt = 0; nt < 8; nt++)
#pragma unroll
            for (int e = 0; e < 4; e++) s[nt][e] = 0.f;

#pragma unroll
        for (int kk = 0; kk < 8; kk++) {
            const int ca = 2 * kk + cHalf;
            unsigned kh4[4][4], kl4[4][4];
#pragma unroll
            for (int p = 0; p < 4; p++) {
                uint32_t kaddr = kvb + fsw(16 * p + rB, ca);
                LDSM_X4(kh4[p][0], kh4[p][1], kh4[p][2], kh4[p][3], kaddr + FKH);
                LDSM_X4(kl4[p][0], kl4[p][1], kl4[p][2], kl4[p][3], kaddr + FKL);
            }
#pragma unroll
            for (int p = 0; p < 4; p++) {
                unsigned bh0[2] = {kh4[p][0], kh4[p][2]};
                unsigned bh1[2] = {kh4[p][1], kh4[p][3]};
                unsigned bl0[2] = {kl4[p][0], kl4[p][2]};
                unsigned bl1[2] = {kl4[p][1], kl4[p][3]};
                mma16816(s[2*p],   qh[kk], bh0);
                mma16816(s[2*p],   ql[kk], bh0);
                mma16816(s[2*p],   qh[kk], bl0);
                mma16816(s[2*p+1], qh[kk], bh1);
                mma16816(s[2*p+1], ql[kk], bh1);
                mma16816(s[2*p+1], qh[kk], bl1);
            }
        }

        if (j0 >= 2 * i0) {
            const int qr0 = i0 * 128 + 16 * w + lr;
            const int kc0 = j0 * 64 + 2 * lq;
#pragma unroll
            for (int nt = 0; nt < 8; nt++)
#pragma unroll
                for (int e = 0; e < 4; e++) {
                    int r = qr0 + (e >> 1) * 8;
                    int c = kc0 + 8 * nt + (e & 1);
                    if (c > r) s[nt][e] = -3.4e38f;
                }
        }

#pragma unroll
        for (int z = 0; z < 2; z++) {
            float mx = -3.4e38f;
#pragma unroll
            for (int nt = 0; nt < 8; nt++)
                mx = fmaxf(mx, fmaxf(s[nt][2*z], s[nt][2*z+1]));
            mx = fmaxf(mx, __shfl_xor_sync(0xffffffffu, mx, 1));
            mx = fmaxf(mx, __shfl_xor_sync(0xffffffffu, mx, 2));
            float mn = fmaxf(mcur[z], mx);
            float alpha = fast_exp(mcur[z] - mn);
            float ls = 0.f;
#pragma unroll
            for (int nt = 0; nt < 8; nt++) {
                float p0 = fast_exp(s[nt][2*z]   - mn);
                float p1 = fast_exp(s[nt][2*z+1] - mn);
                s[nt][2*z] = p0; s[nt][2*z+1] = p1;
                ls += p0 + p1;
            }
            ls += __shfl_xor_sync(0xffffffffu, ls, 1);
            ls += __shfl_xor_sync(0xffffffffu, ls, 2);
            lcur[z] = lcur[z] * alpha + ls;
            mcur[z] = mn;
#pragma unroll
            for (int dt = 0; dt < 16; dt++) {
                o[dt][2*z]   *= alpha;
                o[dt][2*z+1] *= alpha;
            }
        }

        unsigned ph[4][4], pl[4][4];
#pragma unroll
        for (int kk2 = 0; kk2 < 4; kk2++) {
            split2(s[2*kk2][0],   s[2*kk2][1],   ph[kk2][0], pl[kk2][0]);
            split2(s[2*kk2][2],   s[2*kk2][3],   ph[kk2][1], pl[kk2][1]);
            split2(s[2*kk2+1][0], s[2*kk2+1][1], ph[kk2][2], pl[kk2][2]);
            split2(s[2*kk2+1][2], s[2*kk2+1][3], ph[kk2][3], pl[kk2][3]);
        }

#pragma unroll
        for (int kk2 = 0; kk2 < 4; kk2++) {
            const int rV = 16 * kk2 + rB;
#pragma unroll
            for (int p = 0; p < 8; p++) {
                unsigned vh4[4], vl4[4];
                uint32_t vaddr = kvb + fsw(rV, 2 * p + cHalf);
                LDSM_X4_T(vh4[0], vh4[1], vh4[2], vh4[3], vaddr + FVH);
                LDSM_X4_T(vl4[0], vl4[1], vl4[2], vl4[3], vaddr + FVL);
                mma16816(o[2*p],   ph[kk2], &vh4[0]);
                mma16816(o[2*p],   pl[kk2], &vh4[0]);
                mma16816(o[2*p],   ph[kk2], &vl4[0]);
                mma16816(o[2*p+1], ph[kk2], &vh4[2]);
                mma16816(o[2*p+1], pl[kk2], &vh4[2]);
                mma16816(o[2*p+1], ph[kk2], &vl4[2]);
            }
        }
        buf ^= 1;
    }
#undef KV_ISSUE

    const float inv0 = 1.f / lcur[0];
    const float inv1 = 1.f / lcur[1];
    const size_t obase = ((size_t)bh * T_ + (size_t)i0 * 128 + 16 * w + lr) * D_;
#pragma unroll
    for (int dt = 0; dt < 16; dt++) {
        int col = 8 * dt + 2 * lq;
        unsigned h0, l0, h1, l1;
        split2(o[dt][0] * inv0, o[dt][1] * inv0, h0, l0);
        split2(o[dt][2] * inv1, o[dt][3] * inv1, h1, l1);
        *(unsigned*)(g_oh + obase + col)          = h0;
        *(unsigned*)(g_ol + obase + col)          = l0;
        *(unsigned*)(g_oh + obase + 8 * D_ + col) = h1;
        *(unsigned*)(g_ol + obase + 8 * D_ + col) = l1;
    }
}

// ---------------- launch ----------------
extern "C" void kernel_launch(void* const* d_in, const int* in_sizes, int n_in,
                              void* d_out, int out_size)
{
    const float* x    = (const float*)d_in[0];
    const float* Wqkv = (const float*)d_in[1];
    const float* Wout = (const float*)d_in[2];
    float* out = (float*)d_out;

    float* qkv = nullptr;
    cudaGetSymbolAddress((void**)&qkv, g_qkv);
    __nv_bfloat16 *xh, *xl, *w1h, *w1l, *w2h, *w2l, *oh, *ol;
    cudaGetSymbolAddress((void**)&xh,  g_xh);
    cudaGetSymbolAddress((void**)&xl,  g_xl);
    cudaGetSymbolAddress((void**)&w1h, g_w1h);
    cudaGetSymbolAddress((void**)&w1l, g_w1l);
    cudaGetSymbolAddress((void**)&w2h, g_w2h);
    cudaGetSymbolAddress((void**)&w2l, g_w2l);
    cudaGetSymbolAddress((void**)&oh,  g_oh);
    cudaGetSymbolAddress((void**)&ol,  g_ol);

    cudaFuncSetAttribute(mma_gemm, cudaFuncAttributeMaxDynamicSharedMemorySize, GSM_TOTAL);
    cudaFuncSetAttribute(flash_mma_kernel, cudaFuncAttributeMaxDynamicSharedMemorySize, FSM_TOTAL);

    // 0) pre-split inputs to bf16 hi/lo (x, Wqkv, Wout)
    split_kernel<<<(M_ * C_ / 4) / 256, 256>>>(x, xh, xl);
    split_kernel<<<((size_t)C_ * N1_ / 4) / 256, 256>>>(Wqkv, w1h, w1l);
    split_kernel<<<((size_t)C_ * C_ / 4) / 256, 256>>>(Wout, w2h, w2l);
    // 1) QKV projection
    mma_gemm<<<dim3(N1_ / 128, M_ / 128), 256, GSM_TOTAL>>>(xh, xl, w1h, w1l, qkv, M_, N1_, C_);
    // 2) RoPE tables + fused rope/scale/split/transpose
    rope_table_kernel<<<(T_ * HALF_ + 255) / 256, 256>>>();
    convert_kernel<<<(B_ * T_ * H_ * HALF_) / 256, 256>>>();
    // 3) tensor-core causal flash attention
    flash_mma_kernel<<<dim3(T_ / 128, BH_), 256, FSM_TOTAL>>>();
    // 4) output projection
    mma_gemm<<<dim3(C_ / 128, M_ / 128), 256, GSM_TOTAL>>>(oh, ol, w2h, w2l, out, M_, C_, C_);
}